// round 4
// baseline (speedup 1.0000x reference)
#include <cuda_runtime.h>
#include <math.h>

#define NN 50000
#define EE 800000
#define HD 128
#define HSZ (1u<<21)
#define NT 256
#define FULLMASK 0xffffffffu
#define NB 196   // (NN+255)/256

// ---------------- static device scratch ----------------
__device__ float g_xw[NN*HD];
__device__ float g_cv[NN*HD];
__device__ float g_xa[NN*HD];
__device__ float g_xb[NN*HD];
__device__ float g_m0[NN*HD];
__device__ float g_m1[NN*HD];
__device__ float g_m2[NN*HD];
__device__ float g_yb[NN*HD];      // sparse up-gemm output (gathered by cluster)
__device__ float g_p1[NN];         // proj1 (down) / yb2 scalar (up2)
__device__ float g_p2[NN];
__device__ float g_dinv[4][NN];
__device__ float g_ssum[NN];
__device__ float g_scnt[NN];
__device__ int   g_parent[NN];
__device__ int   g_cl[3][NN];
__device__ int   g_act[3][NN];     // active (representative) rows per level
__device__ int   g_nact[3];
__device__ float g_s[EE];
__device__ int   g_esrc[4][EE];
__device__ int   g_edst[4][EE];
__device__ float g_eew[4][EE];
__device__ unsigned g_htab[HSZ];
__device__ float g_xw1[NN];
// CSR per topology
__device__ int   g_coff[4][NN];
__device__ int   g_ccnt[4][NN];
__device__ int   g_csrc[4][EE];
__device__ float g_cnorm[4][EE];
__device__ int   g_cnt[NN];
__device__ int   g_wcur[NN];
__device__ int   g_bsum[256];
__device__ int   g_boff[256];

// ---------------- kernels ----------------

__global__ void k_copy_edges0(const int* __restrict__ ei) {
    int e = blockIdx.x*blockDim.x + threadIdx.x;
    if (e >= EE) return;
    int s = ei[2*e], d = ei[2*e+1];
    g_esrc[0][e] = s;
    g_edst[0][e] = d;
    g_eew[0][e]  = 1.0f;
    atomicAdd(&g_cnt[d], 1);
}

__global__ void k_scan1(int t) {
    __shared__ int sh[256];
    int tx = threadIdx.x;
    int v = blockIdx.x*256 + tx;
    int c = (v < NN) ? g_cnt[v] : 0;
    sh[tx] = c; __syncthreads();
    int val = c;
    for (int o = 1; o < 256; o <<= 1) {
        int y = (tx >= o) ? sh[tx-o] : 0;
        __syncthreads();
        val += y; sh[tx] = val;
        __syncthreads();
    }
    if (v < NN) g_coff[t][v] = val - c;
    if (tx == 255) g_bsum[blockIdx.x] = val;
}

__global__ void k_scan2() {
    __shared__ int sh[256];
    int tx = threadIdx.x;
    int c = (tx < NB) ? g_bsum[tx] : 0;
    sh[tx] = c; __syncthreads();
    int val = c;
    for (int o = 1; o < 256; o <<= 1) {
        int y = (tx >= o) ? sh[tx-o] : 0;
        __syncthreads();
        val += y; sh[tx] = val;
        __syncthreads();
    }
    g_boff[tx] = val - c;
}

__global__ void k_scan3(int t) {
    int v = blockIdx.x*blockDim.x + threadIdx.x;
    if (v >= NN) return;
    int c = g_cnt[v];
    int o = g_coff[t][v] + g_boff[v >> 8];
    g_coff[t][v] = o;
    g_wcur[v]    = o;
    g_ccnt[t][v] = c;
    g_dinv[t][v] = rsqrtf(2.0f + (float)c);
}

__global__ void k_fill(int t) {
    int e = blockIdx.x*blockDim.x + threadIdx.x;
    if (e >= EE) return;
    float w = g_eew[t][e];
    if (w <= 0.0f) return;
    int s = g_esrc[t][e], d = g_edst[t][e];
    int pos = atomicAdd(&g_wcur[d], 1);
    g_csrc[t][pos]  = s;
    g_cnorm[t][pos] = w * g_dinv[t][s] * g_dinv[t][d];
}

// dense register-blocked GEMM: out[N,128] = X[N,kin(stride=kin)] @ W[kin,128]
__global__ void __launch_bounds__(256) k_gemm2(const float* __restrict__ X,
                                               const float* __restrict__ W,
                                               float* __restrict__ out, int kin) {
    __shared__ float Xs[32][65];
    __shared__ float Ws[32][128];
    int row0 = blockIdx.x * 64;
    int tid = threadIdx.x;
    int cid = tid & 31;
    int rid = tid >> 5;
    float acc[8][4];
#pragma unroll
    for (int r = 0; r < 8; r++) { acc[r][0]=0.f; acc[r][1]=0.f; acc[r][2]=0.f; acc[r][3]=0.f; }
    for (int k0 = 0; k0 < kin; k0 += 32) {
        for (int i = tid; i < 64*32; i += 256) {
            int r = i >> 5, kk = i & 31;
            int row = row0 + r;
            Xs[kk][r] = (row < NN) ? X[(size_t)row*kin + k0 + kk] : 0.0f;
        }
        for (int i = tid; i < 32*128; i += 256) {
            int kk = i >> 7, c = i & 127;
            Ws[kk][c] = W[(size_t)(k0+kk)*HD + c];
        }
        __syncthreads();
#pragma unroll
        for (int kk = 0; kk < 32; kk++) {
            float4 w = *(const float4*)&Ws[kk][cid*4];
            float xr[8];
#pragma unroll
            for (int r = 0; r < 8; r++) xr[r] = Xs[kk][rid + 8*r];
#pragma unroll
            for (int r = 0; r < 8; r++) {
                acc[r][0] += xr[r]*w.x; acc[r][1] += xr[r]*w.y;
                acc[r][2] += xr[r]*w.z; acc[r][3] += xr[r]*w.w;
            }
        }
        __syncthreads();
    }
#pragma unroll
    for (int r = 0; r < 8; r++) {
        int row = row0 + rid + 8*r;
        if (row < NN)
            *(float4*)&out[(size_t)row*HD + cid*4] = make_float4(acc[r][0],acc[r][1],acc[r][2],acc[r][3]);
    }
}

// sparse GEMM over active row list (kin=128): out[act[j]] = X[act[j]] @ W
__global__ void __launch_bounds__(256) k_gemm_sp(const float* __restrict__ X,
                                                 const float* __restrict__ W,
                                                 float* __restrict__ out, int L) {
    __shared__ float Xs[32][65];
    __shared__ float Ws[32][128];
    __shared__ int rows[64];
    int count = g_nact[L];
    int row0 = blockIdx.x * 64;
    if (row0 >= count) return;
    int tid = threadIdx.x;
    if (tid < 64) rows[tid] = (row0 + tid < count) ? g_act[L][row0 + tid] : -1;
    __syncthreads();
    int cid = tid & 31;
    int rid = tid >> 5;
    float acc[8][4];
#pragma unroll
    for (int r = 0; r < 8; r++) { acc[r][0]=0.f; acc[r][1]=0.f; acc[r][2]=0.f; acc[r][3]=0.f; }
    for (int k0 = 0; k0 < 128; k0 += 32) {
        for (int i = tid; i < 64*32; i += 256) {
            int r = i >> 5, kk = i & 31;
            int row = rows[r];
            Xs[kk][r] = (row >= 0) ? X[(size_t)row*HD + k0 + kk] : 0.0f;
        }
        for (int i = tid; i < 32*128; i += 256) {
            int kk = i >> 7, c = i & 127;
            Ws[kk][c] = W[(size_t)(k0+kk)*HD + c];
        }
        __syncthreads();
#pragma unroll
        for (int kk = 0; kk < 32; kk++) {
            float4 w = *(const float4*)&Ws[kk][cid*4];
            float xr[8];
#pragma unroll
            for (int r = 0; r < 8; r++) xr[r] = Xs[kk][rid + 8*r];
#pragma unroll
            for (int r = 0; r < 8; r++) {
                acc[r][0] += xr[r]*w.x; acc[r][1] += xr[r]*w.y;
                acc[r][2] += xr[r]*w.z; acc[r][3] += xr[r]*w.w;
            }
        }
        __syncthreads();
    }
#pragma unroll
    for (int r = 0; r < 8; r++) {
        int row = rows[rid + 8*r];
        if (row >= 0)
            *(float4*)&out[(size_t)row*HD + cid*4] = make_float4(acc[r][0],acc[r][1],acc[r][2],acc[r][3]);
    }
}

// CSR gather conv
__global__ void k_conv_gather(int t, const float* __restrict__ b,
                              float* __restrict__ out, int dorelu) {
    int gt = blockIdx.x*blockDim.x + threadIdx.x;
    int v = gt >> 5, lane = gt & 31;
    if (v >= NN) return;
    int off = g_coff[t][v], n = g_ccnt[t][v];
    float4 acc = make_float4(0.f,0.f,0.f,0.f);
    for (int i = 0; i < n; i++) {
        int s   = g_csrc[t][off+i];
        float nm = g_cnorm[t][off+i];
        float4 xv = ((const float4*)(g_xw + (size_t)s*HD))[lane];
        acc.x += xv.x*nm; acc.y += xv.y*nm; acc.z += xv.z*nm; acc.w += xv.w*nm;
    }
    float dv = g_dinv[t][v];
    float sc = 2.0f*dv*dv;
    float4 xs = ((const float4*)(g_xw + (size_t)v*HD))[lane];
    float4 bb = ((const float4*)b)[lane];
    float4 o;
    o.x = acc.x + sc*xs.x + bb.x;
    o.y = acc.y + sc*xs.y + bb.y;
    o.z = acc.z + sc*xs.z + bb.z;
    o.w = acc.w + sc*xs.w + bb.w;
    if (dorelu) {
        o.x = fmaxf(o.x,0.f); o.y = fmaxf(o.y,0.f);
        o.z = fmaxf(o.z,0.f); o.w = fmaxf(o.w,0.f);
    }
    ((float4*)(out + (size_t)v*HD))[lane] = o;
}

// proj + parent init fused
__global__ void k_proj(const float* __restrict__ x, const float* __restrict__ Wp) {
    int gt = blockIdx.x*blockDim.x + threadIdx.x;
    int n = gt >> 5, lane = gt & 31;
    if (n >= NN) return;
    float4 xv = ((const float4*)(x + (size_t)n*HD))[lane];
    float4 w1 = ((const float4*)Wp)[lane];
    float4 w2 = ((const float4*)(Wp + HD))[lane];
    float a = xv.x*w1.x + xv.y*w1.y + xv.z*w1.z + xv.w*w1.w;
    float b = xv.x*w2.x + xv.y*w2.y + xv.z*w2.z + xv.w*w2.w;
#pragma unroll
    for (int o = 16; o > 0; o >>= 1) {
        a += __shfl_xor_sync(FULLMASK, a, o);
        b += __shfl_xor_sync(FULLMASK, b, o);
    }
    if (lane == 0) { g_p1[n] = a; g_p2[n] = b; g_parent[n] = n; }
}

__device__ __forceinline__ int uf_find(int x) {
    while (true) {
        int p = g_parent[x];
        if (p == x) return x;
        int gp = g_parent[p];
        if (gp == p) return p;
        g_parent[x] = gp;  // path halving; parents monotone nonincreasing -> terminates
        x = gp;
    }
}

// fused score + union
__global__ void k_score_union(int t, const float* __restrict__ bp) {
    int e = blockIdx.x*blockDim.x + threadIdx.x;
    if (e >= EE) return;
    float w = g_eew[t][e];
    int s = g_esrc[t][e], d = g_edst[t][e];
    float z = g_p1[s] + g_p2[d] + bp[0];
    float sc = 1.0f / (1.0f + expf(-z));
    bool sel = (w > 0.0f) && (s != d) && (sc > 0.5f);
    g_s[e] = sel ? sc : 0.0f;
    if (!sel) return;
    int ru = uf_find(s);
    int rv = uf_find(d);
    while (ru != rv) {
        if (ru < rv) { int tt = ru; ru = rv; rv = tt; }
        int old = atomicCAS(&g_parent[ru], ru, rv);
        if (old == ru) break;
        ru = uf_find(old);
        rv = uf_find(rv);
    }
}

// flatten + active append + zero pool-scalars
__global__ void k_flatten(int L) {
    int v = blockIdx.x*blockDim.x + threadIdx.x;
    if (v >= NN) return;
    int r = uf_find(v);
    g_cl[L][v] = r;
    g_ssum[v] = 0.0f;
    g_scnt[v] = 0.0f;
    if (r == v) {
        int p = atomicAdd(&g_nact[L], 1);
        g_act[L][p] = v;
    }
}

// fused: seg (score sums by cluster) + relabel/dedup + next-level degree count
__global__ void k_seg_relabel(int tin, int tout, int L) {
    int e = blockIdx.x*blockDim.x + threadIdx.x;
    int lane = threadIdx.x & 31;
    int ns = 0, nd = 0; float nw = 0.0f;
    float s = 0.0f; int c = -1;
    if (e < EE) {
        float w = g_eew[tin][e];
        if (w > 0.0f) {
            int a = g_cl[L][g_esrc[tin][e]];
            int b = g_cl[L][g_edst[tin][e]];
            float sv = g_s[e];
            if (sv > 0.0f) { s = sv; c = a; }   // selected edges are intra-cluster
            if (a != b) {
                unsigned key = (unsigned)a * (unsigned)NN + (unsigned)b;
                unsigned h = (unsigned)(((unsigned long long)key * 2654435761u) >> 11) & (HSZ-1);
                while (true) {
                    unsigned old = atomicCAS(&g_htab[h], 0xFFFFFFFFu, key);
                    if (old == 0xFFFFFFFFu) {
                        ns = a; nd = b; nw = 1.0f;
                        atomicAdd(&g_cnt[b], 1);
                        break;
                    }
                    if (old == key) break;
                    h = (h + 1) & (HSZ-1);
                }
            }
        }
        g_esrc[tout][e] = ns; g_edst[tout][e] = nd; g_eew[tout][e] = nw;
    }
    // warp-aggregated segment add
    unsigned m = __match_any_sync(FULLMASK, c);
    int leader = __ffs(m) - 1;
    float tot = 0.0f;
#pragma unroll
    for (int j = 0; j < 32; j++) {
        float os = __shfl_sync(FULLMASK, s, j);
        int   oc = __shfl_sync(FULLMASK, c, j);
        if (lane == leader && c >= 0 && oc == c) tot += os;
    }
    if (lane == leader && c >= 0) {
        atomicAdd(&g_ssum[c], tot);
        atomicAdd(&g_scnt[c], (float)__popc(m));
    }
}

__global__ void k_nodeacc(int L, const float* __restrict__ x, float* __restrict__ xn) {
    int i = blockIdx.x*blockDim.x + threadIdx.x;
    if (i >= NN*32) return;
    int v = i >> 5, f4 = i & 31;
    float4 val = ((const float4*)(x + (size_t)v*HD))[f4];
    atomicAdd(((float4*)(xn + (size_t)g_cl[L][v]*HD)) + f4, val);
}

__global__ void k_scale(float* __restrict__ xn) {
    int i = blockIdx.x*blockDim.x + threadIdx.x;
    if (i >= NN*HD) return;
    int v = i >> 7;
    float c = g_scnt[v];
    float w = (c > 0.0f) ? g_ssum[v] / fmaxf(c, 1.0f) : 1.0f;
    xn[i] *= w;
}

// g_xw[v] += g_yb[cl[L][v]]
__global__ void k_addg(int L) {
    int i = blockIdx.x*blockDim.x + threadIdx.x;
    if (i >= NN*32) return;
    int v = i >> 5, f4 = i & 31;
    float4 y = ((const float4*)(g_yb + (size_t)g_cl[L][v]*HD))[f4];
    float4* o = ((float4*)(g_xw + (size_t)v*HD)) + f4;
    float4 x = *o;
    x.x += y.x; x.y += y.y; x.z += y.z; x.w += y.w;
    *o = x;
}

// yb2 scalar: for active rows of level 0: g_p1[row] = dot(xup[row], Wu2[256:384])
__global__ void k_yb2(const float* __restrict__ xup, const float* __restrict__ Wu2c) {
    int gt = blockIdx.x*blockDim.x + threadIdx.x;
    int j = gt >> 5, lane = gt & 31;
    if (j >= g_nact[0]) return;
    int row = g_act[0][j];
    float4 xv = ((const float4*)(xup + (size_t)row*HD))[lane];
    float4 wv = ((const float4*)Wu2c)[lane];
    float a = xv.x*wv.x + xv.y*wv.y + xv.z*wv.z + xv.w*wv.w;
#pragma unroll
    for (int o = 16; o > 0; o >>= 1) a += __shfl_xor_sync(FULLMASK, a, o);
    if (lane == 0) g_p1[row] = a;
}

// final scalar proj: xw1[v] = m0[v].Wu2[0:128] + x_in[v].Wu2[128:256] + yb2[cl0[v]]
__global__ void k_xw1(const float* __restrict__ m0, const float* __restrict__ xin,
                      const float* __restrict__ Wu2) {
    int gt = blockIdx.x*blockDim.x + threadIdx.x;
    int v = gt >> 5, lane = gt & 31;
    if (v >= NN) return;
    float4 x1 = ((const float4*)(m0  + (size_t)v*HD))[lane];
    float4 x2 = ((const float4*)(xin + (size_t)v*HD))[lane];
    float4 w1 = ((const float4*)Wu2)[lane];
    float4 w2 = ((const float4*)(Wu2 + HD))[lane];
    float a = x1.x*w1.x + x1.y*w1.y + x1.z*w1.z + x1.w*w1.w
            + x2.x*w2.x + x2.y*w2.y + x2.z*w2.z + x2.w*w2.w;
#pragma unroll
    for (int o = 16; o > 0; o >>= 1) a += __shfl_xor_sync(FULLMASK, a, o);
    if (lane == 0) g_xw1[v] = a + g_p1[g_cl[0][v]];
}

__global__ void k_conv1(const float* __restrict__ bu, float* __restrict__ out) {
    int gt = blockIdx.x*blockDim.x + threadIdx.x;
    int v = gt >> 5, lane = gt & 31;
    if (v >= NN) return;
    int off = g_coff[0][v], n = g_ccnt[0][v];
    float acc = 0.0f;
    for (int i = lane; i < n; i += 32)
        acc += g_xw1[g_csrc[0][off+i]] * g_cnorm[0][off+i];
#pragma unroll
    for (int o = 16; o > 0; o >>= 1) acc += __shfl_xor_sync(FULLMASK, acc, o);
    if (lane == 0) {
        float dv = g_dinv[0][v];
        float z = acc + 2.0f*dv*dv*g_xw1[v] + bu[0];
        out[v] = 1.0f / (1.0f + expf(-z));
    }
}

// ---------------- host orchestration ----------------

extern "C" void kernel_launch(void* const* d_in, const int* in_sizes, int n_in,
                              void* d_out, int out_size) {
    (void)in_sizes; (void)n_in; (void)out_size;
    const float* x_in = (const float*)d_in[0];
    const int*   ei   = (const int*)d_in[1];
    const float* Wd[4] = {(const float*)d_in[3],(const float*)d_in[5],(const float*)d_in[7],(const float*)d_in[9]};
    const float* bd[4] = {(const float*)d_in[4],(const float*)d_in[6],(const float*)d_in[8],(const float*)d_in[10]};
    const float* Wp[3] = {(const float*)d_in[11],(const float*)d_in[13],(const float*)d_in[15]};
    const float* bp[3] = {(const float*)d_in[12],(const float*)d_in[14],(const float*)d_in[16]};
    const float* Wu[3] = {(const float*)d_in[17],(const float*)d_in[19],(const float*)d_in[21]};
    const float* bu[3] = {(const float*)d_in[18],(const float*)d_in[20],(const float*)d_in[22]};
    float* out = (float*)d_out;

    void* pv;
    float *p_xa, *p_xb, *p_cv, *p_m0, *p_m1, *p_m2, *p_xw, *p_yb;
    int *p_cnt, *p_nact; unsigned *p_htab;
    cudaGetSymbolAddress(&pv, g_xa);   p_xa   = (float*)pv;
    cudaGetSymbolAddress(&pv, g_xb);   p_xb   = (float*)pv;
    cudaGetSymbolAddress(&pv, g_cv);   p_cv   = (float*)pv;
    cudaGetSymbolAddress(&pv, g_m0);   p_m0   = (float*)pv;
    cudaGetSymbolAddress(&pv, g_m1);   p_m1   = (float*)pv;
    cudaGetSymbolAddress(&pv, g_m2);   p_m2   = (float*)pv;
    cudaGetSymbolAddress(&pv, g_xw);   p_xw   = (float*)pv;
    cudaGetSymbolAddress(&pv, g_yb);   p_yb   = (float*)pv;
    cudaGetSymbolAddress(&pv, g_cnt);  p_cnt  = (int*)pv;
    cudaGetSymbolAddress(&pv, g_nact); p_nact = (int*)pv;
    cudaGetSymbolAddress(&pv, g_htab); p_htab = (unsigned*)pv;

    const int gN  = (NN + NT - 1) / NT;
    const int gNF = (NN*HD + NT - 1) / NT;
    const int gN4 = (NN*32 + NT - 1) / NT;
    const int gE  = (EE + NT - 1) / NT;
    const int gNw = (NN*32 + NT - 1) / NT;
    const int gG  = (NN + 63) / 64;

    cudaMemsetAsync(p_cnt, 0, NN*sizeof(int));
    cudaMemsetAsync(p_nact, 0, 3*sizeof(int));
    k_copy_edges0<<<gE, NT>>>(ei);

    const float* Xin[3]  = { x_in, p_xa, p_xb };
    float*       memb[3] = { p_m0, p_m1, p_m2 };
    float*       xout[3] = { p_xa, p_xb, p_xa };
    for (int i = 0; i < 3; i++) {
        int t = i;
        k_scan1<<<NB, 256>>>(t);
        k_scan2<<<1, 256>>>();
        if (i == 0) {
            k_gemm2<<<gG, 256>>>(x_in, Wd[0], p_xw, 128);
        } else {
            cudaMemsetAsync(p_xw, 0, (size_t)NN*HD*sizeof(float));
            k_gemm_sp<<<gG, 256>>>(Xin[i], Wd[i], p_xw, i-1);
        }
        k_scan3<<<gN, NT>>>(t);
        k_fill<<<gE, NT>>>(t);
        k_conv_gather<<<gNw, NT>>>(t, bd[i], memb[i], 1);
        // pooling
        k_proj<<<gNw, NT>>>(memb[i], Wp[i]);
        k_score_union<<<gE, NT>>>(t, bp[i]);
        k_flatten<<<gN, NT>>>(i);
        cudaMemsetAsync(xout[i], 0, (size_t)NN*HD*sizeof(float));
        cudaMemsetAsync(p_htab, 0xFF, HSZ*sizeof(unsigned));
        cudaMemsetAsync(p_cnt, 0, NN*sizeof(int));
        k_seg_relabel<<<gE, NT>>>(t, t+1, i);
        k_nodeacc<<<gN4, NT>>>(i, memb[i], xout[i]);
        k_scale<<<gNF, NT>>>(xout[i]);
    }

    // ---- bottom conv (topology 3) ----
    k_scan1<<<NB, 256>>>(3);
    k_scan2<<<1, 256>>>();
    cudaMemsetAsync(p_xw, 0, (size_t)NN*HD*sizeof(float));
    k_gemm_sp<<<gG, 256>>>(p_xa, Wd[3], p_xw, 2);
    k_scan3<<<gN, NT>>>(3);
    k_fill<<<gE, NT>>>(3);
    k_conv_gather<<<gNw, NT>>>(3, bd[3], p_cv, 0);

    // ---- UP 0 : level L=2, topology 2 ----
    k_gemm2<<<gG, 256>>>(p_m2, Wu[0], p_xw, 128);                 // mem @ Wu_top
    k_gemm_sp<<<gG, 256>>>(p_cv, Wu[0] + 128*HD, p_yb, 2);        // xup @ Wu_bot (sparse)
    k_addg<<<gN4, NT>>>(2);
    k_conv_gather<<<gNw, NT>>>(2, bu[0], p_xa, 1);

    // ---- UP 1 : level L=1, topology 1 ----
    k_gemm2<<<gG, 256>>>(p_m1, Wu[1], p_xw, 128);
    k_gemm_sp<<<gG, 256>>>(p_xa, Wu[1] + 128*HD, p_yb, 1);
    k_addg<<<gN4, NT>>>(1);
    k_conv_gather<<<gNw, NT>>>(1, bu[1], p_xb, 1);

    // ---- UP 2 : level L=0, topology 0, output dim 1 ----
    k_yb2<<<gNw, NT>>>(p_xb, Wu[2] + 256);
    k_xw1<<<gNw, NT>>>(p_m0, x_in, Wu[2]);
    k_conv1<<<gNw, NT>>>(bu[2], out);
}

// round 5
// speedup vs baseline: 1.1538x; 1.1538x over previous
#include <cuda_runtime.h>
#include <math.h>

#define NN 50000
#define EE 800000
#define HD 128
#define HSZ (1u<<21)
#define NT 256
#define FULLMASK 0xffffffffu
#define NB 196   // (NN+255)/256

// ---------------- static device scratch ----------------
__device__ float g_xw[NN*HD];
__device__ float g_cv[NN*HD];
__device__ float g_xa[NN*HD];
__device__ float g_xb[NN*HD];
__device__ float g_m0[NN*HD];
__device__ float g_m1[NN*HD];
__device__ float g_m2[NN*HD];
__device__ float g_yb[NN*HD];
__device__ float g_p1[NN];
__device__ float g_p2[NN];
__device__ float g_dinv[4][NN];
__device__ float g_ssum[NN];
__device__ float g_scnt[NN];
__device__ int   g_parent[NN];
__device__ int   g_cl[3][NN];
__device__ int   g_act[3][NN];
__device__ int   g_nact[3];
__device__ float g_s[EE];
__device__ int   g_esrc[4][EE];
__device__ int   g_edst[4][EE];
__device__ float g_eew[4][EE];
__device__ unsigned g_htab[HSZ];
__device__ float g_xw1[NN];
__device__ int   g_coff[4][NN];
__device__ int   g_ccnt[4][NN];
__device__ int   g_csrc[4][EE];
__device__ float g_cnorm[4][EE];
__device__ int   g_cnt[NN];
__device__ int   g_wcur[NN];
__device__ int   g_bsum[256];
__device__ int   g_boff[256];

// ---------------- kernels ----------------

__global__ void k_copy_edges0(const int* __restrict__ ei) {
    int e = blockIdx.x*blockDim.x + threadIdx.x;
    if (e >= EE) return;
    int s = ei[2*e], d = ei[2*e+1];
    g_esrc[0][e] = s;
    g_edst[0][e] = d;
    g_eew[0][e]  = 1.0f;
    atomicAdd(&g_cnt[d], 1);
}

__global__ void k_scan1(int t) {
    __shared__ int sh[256];
    int tx = threadIdx.x;
    int v = blockIdx.x*256 + tx;
    int c = (v < NN) ? g_cnt[v] : 0;
    sh[tx] = c; __syncthreads();
    int val = c;
    for (int o = 1; o < 256; o <<= 1) {
        int y = (tx >= o) ? sh[tx-o] : 0;
        __syncthreads();
        val += y; sh[tx] = val;
        __syncthreads();
    }
    if (v < NN) g_coff[t][v] = val - c;
    if (tx == 255) g_bsum[blockIdx.x] = val;
}

__global__ void k_scan2() {
    __shared__ int sh[256];
    int tx = threadIdx.x;
    int c = (tx < NB) ? g_bsum[tx] : 0;
    sh[tx] = c; __syncthreads();
    int val = c;
    for (int o = 1; o < 256; o <<= 1) {
        int y = (tx >= o) ? sh[tx-o] : 0;
        __syncthreads();
        val += y; sh[tx] = val;
        __syncthreads();
    }
    g_boff[tx] = val - c;
}

__global__ void k_scan3(int t) {
    int v = blockIdx.x*blockDim.x + threadIdx.x;
    if (v >= NN) return;
    int c = g_cnt[v];
    int o = g_coff[t][v] + g_boff[v >> 8];
    g_coff[t][v] = o;
    g_wcur[v]    = o;
    g_ccnt[t][v] = c;
    g_dinv[t][v] = rsqrtf(2.0f + (float)c);
}

__global__ void k_fill(int t) {
    int e = blockIdx.x*blockDim.x + threadIdx.x;
    if (e >= EE) return;
    float w = g_eew[t][e];
    if (w <= 0.0f) return;
    int s = g_esrc[t][e], d = g_edst[t][e];
    int pos = atomicAdd(&g_wcur[d], 1);
    g_csrc[t][pos]  = s;
    g_cnorm[t][pos] = w * g_dinv[t][s] * g_dinv[t][d];
}

// unified 128x128-tile GEMM (kin = 128). L < 0: dense rows; L >= 0: rows from g_act[L].
__global__ void __launch_bounds__(256) k_gemmT(const float* __restrict__ X,
                                               const float* __restrict__ W,
                                               float* __restrict__ out, int L) {
    __shared__ float Xs[32][132];
    __shared__ float Ws[32][128];
    __shared__ int rows[128];
    int count = (L >= 0) ? g_nact[L] : NN;
    int row0 = blockIdx.x * 128;
    if (row0 >= count) return;
    int tid = threadIdx.x;
    if (tid < 128) {
        int rr = row0 + tid;
        rows[tid] = (rr < count) ? ((L >= 0) ? g_act[L][rr] : rr) : -1;
    }
    __syncthreads();
    int cid = tid & 31;   // col group: cols cid*4 .. cid*4+3
    int rid = tid >> 5;   // row slot: rows rid + 8*r
    float acc[16][4];
#pragma unroll
    for (int r = 0; r < 16; r++) { acc[r][0]=0.f; acc[r][1]=0.f; acc[r][2]=0.f; acc[r][3]=0.f; }
    for (int k0 = 0; k0 < HD; k0 += 32) {
        // Xs fill: 128 rows x 32 k, transposed store
        for (int i = tid; i < 128*8; i += 256) {
            int r = i >> 3, q = i & 7;
            int row = rows[r];
            float4 v = make_float4(0.f,0.f,0.f,0.f);
            if (row >= 0) v = *(const float4*)&X[(size_t)row*HD + k0 + q*4];
            Xs[q*4+0][r] = v.x; Xs[q*4+1][r] = v.y;
            Xs[q*4+2][r] = v.z; Xs[q*4+3][r] = v.w;
        }
        for (int i = tid; i < 32*128; i += 256) {
            int kk = i >> 7, c = i & 127;
            Ws[kk][c] = W[(size_t)(k0+kk)*HD + c];
        }
        __syncthreads();
#pragma unroll
        for (int kk = 0; kk < 32; kk++) {
            float4 w = *(const float4*)&Ws[kk][cid*4];
#pragma unroll
            for (int r = 0; r < 16; r++) {
                float xr = Xs[kk][rid + 8*r];
                acc[r][0] += xr*w.x; acc[r][1] += xr*w.y;
                acc[r][2] += xr*w.z; acc[r][3] += xr*w.w;
            }
        }
        __syncthreads();
    }
#pragma unroll
    for (int r = 0; r < 16; r++) {
        int row = rows[rid + 8*r];
        if (row >= 0)
            *(float4*)&out[(size_t)row*HD + cid*4] = make_float4(acc[r][0],acc[r][1],acc[r][2],acc[r][3]);
    }
}

// CSR gather conv
__global__ void k_conv_gather(int t, const float* __restrict__ b,
                              float* __restrict__ out, int dorelu) {
    int gt = blockIdx.x*blockDim.x + threadIdx.x;
    int v = gt >> 5, lane = gt & 31;
    if (v >= NN) return;
    int off = g_coff[t][v], n = g_ccnt[t][v];
    float4 acc = make_float4(0.f,0.f,0.f,0.f);
    for (int i = 0; i < n; i++) {
        int s   = g_csrc[t][off+i];
        float nm = g_cnorm[t][off+i];
        float4 xv = ((const float4*)(g_xw + (size_t)s*HD))[lane];
        acc.x += xv.x*nm; acc.y += xv.y*nm; acc.z += xv.z*nm; acc.w += xv.w*nm;
    }
    float dv = g_dinv[t][v];
    float sc = 2.0f*dv*dv;
    float4 xs = ((const float4*)(g_xw + (size_t)v*HD))[lane];
    float4 bb = ((const float4*)b)[lane];
    float4 o;
    o.x = acc.x + sc*xs.x + bb.x;
    o.y = acc.y + sc*xs.y + bb.y;
    o.z = acc.z + sc*xs.z + bb.z;
    o.w = acc.w + sc*xs.w + bb.w;
    if (dorelu) {
        o.x = fmaxf(o.x,0.f); o.y = fmaxf(o.y,0.f);
        o.z = fmaxf(o.z,0.f); o.w = fmaxf(o.w,0.f);
    }
    ((float4*)(out + (size_t)v*HD))[lane] = o;
}

// proj + parent init fused
__global__ void k_proj(const float* __restrict__ x, const float* __restrict__ Wp) {
    int gt = blockIdx.x*blockDim.x + threadIdx.x;
    int n = gt >> 5, lane = gt & 31;
    if (n >= NN) return;
    float4 xv = ((const float4*)(x + (size_t)n*HD))[lane];
    float4 w1 = ((const float4*)Wp)[lane];
    float4 w2 = ((const float4*)(Wp + HD))[lane];
    float a = xv.x*w1.x + xv.y*w1.y + xv.z*w1.z + xv.w*w1.w;
    float b = xv.x*w2.x + xv.y*w2.y + xv.z*w2.z + xv.w*w2.w;
#pragma unroll
    for (int o = 16; o > 0; o >>= 1) {
        a += __shfl_xor_sync(FULLMASK, a, o);
        b += __shfl_xor_sync(FULLMASK, b, o);
    }
    if (lane == 0) { g_p1[n] = a; g_p2[n] = b; g_parent[n] = n; }
}

// volatile loads: L1 is NOT coherent across SMs; plain loads can spin on stale
// parents (R4 regression). volatile -> L2-fresh reads.
__device__ __forceinline__ int uf_find(int x) {
    volatile int* P = g_parent;
    while (true) {
        int p = P[x];
        if (p == x) return x;
        int gp = P[p];
        if (gp == p) return p;
        P[x] = gp;   // path halving; benign race (gp is an ancestor)
        x = gp;
    }
}

// fused score + union
__global__ void k_score_union(int t, const float* __restrict__ bp) {
    int e = blockIdx.x*blockDim.x + threadIdx.x;
    if (e >= EE) return;
    float w = g_eew[t][e];
    int s = g_esrc[t][e], d = g_edst[t][e];
    float z = g_p1[s] + g_p2[d] + bp[0];
    float sc = 1.0f / (1.0f + expf(-z));
    bool sel = (w > 0.0f) && (s != d) && (sc > 0.5f);
    g_s[e] = sel ? sc : 0.0f;
    if (!sel) return;
    int ru = uf_find(s);
    int rv = uf_find(d);
    while (ru != rv) {
        if (ru < rv) { int tt = ru; ru = rv; rv = tt; }
        int old = atomicCAS(&g_parent[ru], ru, rv);
        if (old == ru) break;
        ru = uf_find(old);
        rv = uf_find(rv);
    }
}

__global__ void k_flatten(int L) {
    int v = blockIdx.x*blockDim.x + threadIdx.x;
    if (v >= NN) return;
    int r = uf_find(v);
    g_cl[L][v] = r;
    g_ssum[v] = 0.0f;
    g_scnt[v] = 0.0f;
    if (r == v) {
        int p = atomicAdd(&g_nact[L], 1);
        g_act[L][p] = v;
    }
}

// fused: seg + relabel/dedup + next-level degree count
__global__ void k_seg_relabel(int tin, int tout, int L) {
    int e = blockIdx.x*blockDim.x + threadIdx.x;
    int lane = threadIdx.x & 31;
    int ns = 0, nd = 0; float nw = 0.0f;
    float s = 0.0f; int c = -1;
    if (e < EE) {
        float w = g_eew[tin][e];
        if (w > 0.0f) {
            int a = g_cl[L][g_esrc[tin][e]];
            int b = g_cl[L][g_edst[tin][e]];
            float sv = g_s[e];
            if (sv > 0.0f) { s = sv; c = a; }
            if (a != b) {
                unsigned key = (unsigned)a * (unsigned)NN + (unsigned)b;
                unsigned h = (unsigned)(((unsigned long long)key * 2654435761u) >> 11) & (HSZ-1);
                while (true) {
                    unsigned old = atomicCAS(&g_htab[h], 0xFFFFFFFFu, key);
                    if (old == 0xFFFFFFFFu) {
                        ns = a; nd = b; nw = 1.0f;
                        atomicAdd(&g_cnt[b], 1);
                        break;
                    }
                    if (old == key) break;
                    h = (h + 1) & (HSZ-1);
                }
            }
        }
        g_esrc[tout][e] = ns; g_edst[tout][e] = nd; g_eew[tout][e] = nw;
    }
    unsigned m = __match_any_sync(FULLMASK, c);
    int leader = __ffs(m) - 1;
    float tot = 0.0f;
#pragma unroll
    for (int j = 0; j < 32; j++) {
        float os = __shfl_sync(FULLMASK, s, j);
        int   oc = __shfl_sync(FULLMASK, c, j);
        if (lane == leader && c >= 0 && oc == c) tot += os;
    }
    if (lane == leader && c >= 0) {
        atomicAdd(&g_ssum[c], tot);
        atomicAdd(&g_scnt[c], (float)__popc(m));
    }
}

__global__ void k_nodeacc(int L, const float* __restrict__ x, float* __restrict__ xn) {
    int i = blockIdx.x*blockDim.x + threadIdx.x;
    if (i >= NN*32) return;
    int v = i >> 5, f4 = i & 31;
    float4 val = ((const float4*)(x + (size_t)v*HD))[f4];
    atomicAdd(((float4*)(xn + (size_t)g_cl[L][v]*HD)) + f4, val);
}

__global__ void k_scale(float* __restrict__ xn) {
    int i = blockIdx.x*blockDim.x + threadIdx.x;
    if (i >= NN*HD) return;
    int v = i >> 7;
    float c = g_scnt[v];
    float w = (c > 0.0f) ? g_ssum[v] / fmaxf(c, 1.0f) : 1.0f;
    xn[i] *= w;
}

__global__ void k_addg(int L) {
    int i = blockIdx.x*blockDim.x + threadIdx.x;
    if (i >= NN*32) return;
    int v = i >> 5, f4 = i & 31;
    float4 y = ((const float4*)(g_yb + (size_t)g_cl[L][v]*HD))[f4];
    float4* o = ((float4*)(g_xw + (size_t)v*HD)) + f4;
    float4 x = *o;
    x.x += y.x; x.y += y.y; x.z += y.z; x.w += y.w;
    *o = x;
}

__global__ void k_yb2(const float* __restrict__ xup, const float* __restrict__ Wu2c) {
    int gt = blockIdx.x*blockDim.x + threadIdx.x;
    int j = gt >> 5, lane = gt & 31;
    if (j >= g_nact[0]) return;
    int row = g_act[0][j];
    float4 xv = ((const float4*)(xup + (size_t)row*HD))[lane];
    float4 wv = ((const float4*)Wu2c)[lane];
    float a = xv.x*wv.x + xv.y*wv.y + xv.z*wv.z + xv.w*wv.w;
#pragma unroll
    for (int o = 16; o > 0; o >>= 1) a += __shfl_xor_sync(FULLMASK, a, o);
    if (lane == 0) g_p1[row] = a;
}

__global__ void k_xw1(const float* __restrict__ m0, const float* __restrict__ xin,
                      const float* __restrict__ Wu2) {
    int gt = blockIdx.x*blockDim.x + threadIdx.x;
    int v = gt >> 5, lane = gt & 31;
    if (v >= NN) return;
    float4 x1 = ((const float4*)(m0  + (size_t)v*HD))[lane];
    float4 x2 = ((const float4*)(xin + (size_t)v*HD))[lane];
    float4 w1 = ((const float4*)Wu2)[lane];
    float4 w2 = ((const float4*)(Wu2 + HD))[lane];
    float a = x1.x*w1.x + x1.y*w1.y + x1.z*w1.z + x1.w*w1.w
            + x2.x*w2.x + x2.y*w2.y + x2.z*w2.z + x2.w*w2.w;
#pragma unroll
    for (int o = 16; o > 0; o >>= 1) a += __shfl_xor_sync(FULLMASK, a, o);
    if (lane == 0) g_xw1[v] = a + g_p1[g_cl[0][v]];
}

__global__ void k_conv1(const float* __restrict__ bu, float* __restrict__ out) {
    int gt = blockIdx.x*blockDim.x + threadIdx.x;
    int v = gt >> 5, lane = gt & 31;
    if (v >= NN) return;
    int off = g_coff[0][v], n = g_ccnt[0][v];
    float acc = 0.0f;
    for (int i = lane; i < n; i += 32)
        acc += g_xw1[g_csrc[0][off+i]] * g_cnorm[0][off+i];
#pragma unroll
    for (int o = 16; o > 0; o >>= 1) acc += __shfl_xor_sync(FULLMASK, acc, o);
    if (lane == 0) {
        float dv = g_dinv[0][v];
        float z = acc + 2.0f*dv*dv*g_xw1[v] + bu[0];
        out[v] = 1.0f / (1.0f + expf(-z));
    }
}

// ---------------- host orchestration ----------------

extern "C" void kernel_launch(void* const* d_in, const int* in_sizes, int n_in,
                              void* d_out, int out_size) {
    (void)in_sizes; (void)n_in; (void)out_size;
    const float* x_in = (const float*)d_in[0];
    const int*   ei   = (const int*)d_in[1];
    const float* Wd[4] = {(const float*)d_in[3],(const float*)d_in[5],(const float*)d_in[7],(const float*)d_in[9]};
    const float* bd[4] = {(const float*)d_in[4],(const float*)d_in[6],(const float*)d_in[8],(const float*)d_in[10]};
    const float* Wp[3] = {(const float*)d_in[11],(const float*)d_in[13],(const float*)d_in[15]};
    const float* bp[3] = {(const float*)d_in[12],(const float*)d_in[14],(const float*)d_in[16]};
    const float* Wu[3] = {(const float*)d_in[17],(const float*)d_in[19],(const float*)d_in[21]};
    const float* bu[3] = {(const float*)d_in[18],(const float*)d_in[20],(const float*)d_in[22]};
    float* out = (float*)d_out;

    void* pv;
    float *p_xa, *p_xb, *p_cv, *p_m0, *p_m1, *p_m2, *p_xw, *p_yb;
    int *p_cnt, *p_nact; unsigned *p_htab;
    cudaGetSymbolAddress(&pv, g_xa);   p_xa   = (float*)pv;
    cudaGetSymbolAddress(&pv, g_xb);   p_xb   = (float*)pv;
    cudaGetSymbolAddress(&pv, g_cv);   p_cv   = (float*)pv;
    cudaGetSymbolAddress(&pv, g_m0);   p_m0   = (float*)pv;
    cudaGetSymbolAddress(&pv, g_m1);   p_m1   = (float*)pv;
    cudaGetSymbolAddress(&pv, g_m2);   p_m2   = (float*)pv;
    cudaGetSymbolAddress(&pv, g_xw);   p_xw   = (float*)pv;
    cudaGetSymbolAddress(&pv, g_yb);   p_yb   = (float*)pv;
    cudaGetSymbolAddress(&pv, g_cnt);  p_cnt  = (int*)pv;
    cudaGetSymbolAddress(&pv, g_nact); p_nact = (int*)pv;
    cudaGetSymbolAddress(&pv, g_htab); p_htab = (unsigned*)pv;

    const int gN  = (NN + NT - 1) / NT;
    const int gNF = (NN*HD + NT - 1) / NT;
    const int gN4 = (NN*32 + NT - 1) / NT;
    const int gE  = (EE + NT - 1) / NT;
    const int gNw = (NN*32 + NT - 1) / NT;
    const int gG  = (NN + 127) / 128;

    cudaMemsetAsync(p_cnt, 0, NN*sizeof(int));
    cudaMemsetAsync(p_nact, 0, 3*sizeof(int));
    k_copy_edges0<<<gE, NT>>>(ei);

    const float* Xin[3]  = { x_in, p_xa, p_xb };
    float*       memb[3] = { p_m0, p_m1, p_m2 };
    float*       xout[3] = { p_xa, p_xb, p_xa };
    for (int i = 0; i < 3; i++) {
        int t = i;
        k_scan1<<<NB, 256>>>(t);
        k_scan2<<<1, 256>>>();
        if (i == 0) {
            k_gemmT<<<gG, 256>>>(x_in, Wd[0], p_xw, -1);
        } else {
            cudaMemsetAsync(p_xw, 0, (size_t)NN*HD*sizeof(float));
            k_gemmT<<<gG, 256>>>(Xin[i], Wd[i], p_xw, i-1);
        }
        k_scan3<<<gN, NT>>>(t);
        k_fill<<<gE, NT>>>(t);
        k_conv_gather<<<gNw, NT>>>(t, bd[i], memb[i], 1);
        // pooling
        k_proj<<<gNw, NT>>>(memb[i], Wp[i]);
        k_score_union<<<gE, NT>>>(t, bp[i]);
        k_flatten<<<gN, NT>>>(i);
        cudaMemsetAsync(xout[i], 0, (size_t)NN*HD*sizeof(float));
        cudaMemsetAsync(p_htab, 0xFF, HSZ*sizeof(unsigned));
        cudaMemsetAsync(p_cnt, 0, NN*sizeof(int));
        k_seg_relabel<<<gE, NT>>>(t, t+1, i);
        k_nodeacc<<<gN4, NT>>>(i, memb[i], xout[i]);
        k_scale<<<gNF, NT>>>(xout[i]);
    }

    // ---- bottom conv (topology 3) ----
    k_scan1<<<NB, 256>>>(3);
    k_scan2<<<1, 256>>>();
    cudaMemsetAsync(p_xw, 0, (size_t)NN*HD*sizeof(float));
    k_gemmT<<<gG, 256>>>(p_xa, Wd[3], p_xw, 2);
    k_scan3<<<gN, NT>>>(3);
    k_fill<<<gE, NT>>>(3);
    k_conv_gather<<<gNw, NT>>>(3, bd[3], p_cv, 0);

    // ---- UP 0 : level L=2, topology 2 ----
    k_gemmT<<<gG, 256>>>(p_m2, Wu[0], p_xw, -1);             // mem @ Wu_top
    k_gemmT<<<gG, 256>>>(p_cv, Wu[0] + 128*HD, p_yb, 2);     // xup @ Wu_bot (sparse)
    k_addg<<<gN4, NT>>>(2);
    k_conv_gather<<<gNw, NT>>>(2, bu[0], p_xa, 1);

    // ---- UP 1 : level L=1, topology 1 ----
    k_gemmT<<<gG, 256>>>(p_m1, Wu[1], p_xw, -1);
    k_gemmT<<<gG, 256>>>(p_xa, Wu[1] + 128*HD, p_yb, 1);
    k_addg<<<gN4, NT>>>(1);
    k_conv_gather<<<gNw, NT>>>(1, bu[1], p_xb, 1);

    // ---- UP 2 : level L=0, topology 0, output dim 1 ----
    k_yb2<<<gNw, NT>>>(p_xb, Wu[2] + 256);
    k_xw1<<<gNw, NT>>>(p_m0, x_in, Wu[2]);
    k_conv1<<<gNw, NT>>>(bu[2], out);
}

// round 6
// speedup vs baseline: 1.5021x; 1.3019x over previous
#include <cuda_runtime.h>
#include <math.h>

#define NN 50000
#define EE 800000
#define HD 128
#define HSZ (1u<<21)
#define NT 256
#define FULLMASK 0xffffffffu
#define NB 196   // (NN+255)/256

// ---------------- static device scratch ----------------
__device__ float g_xw[NN*HD];
__device__ float g_cv[NN*HD];
__device__ float g_xa[NN*HD];
__device__ float g_xb[NN*HD];
__device__ float g_m0[NN*HD];
__device__ float g_m1[NN*HD];
__device__ float g_m2[NN*HD];
__device__ float g_yb[NN*HD];
__device__ float g_p1[NN];
__device__ float g_p2[NN];
__device__ float g_dinv[4][NN];
__device__ float g_ssum[NN];
__device__ float g_scnt[NN];
__device__ int   g_parent[NN];
__device__ int   g_cl[3][NN];
__device__ int   g_act[3][NN];
__device__ int   g_nact[3];
__device__ unsigned char g_isact[3][NN];
__device__ float g_s[EE];
__device__ int   g_esrc[4][EE];
__device__ int   g_edst[4][EE];
__device__ float g_eew[4][EE];
__device__ unsigned g_htab[HSZ];
__device__ float g_xw1[NN];
__device__ int   g_coff[4][NN];
__device__ int   g_ccnt[4][NN];
__device__ int   g_csrc[4][EE];
__device__ float g_cnorm[4][EE];
__device__ int   g_cnt[NN];
__device__ int   g_wcur[NN];
__device__ int   g_bsum[256];
__device__ int   g_boff[256];
// member sort for pooling
__device__ int   g_mcnt[NN];
__device__ int   g_moff[NN];
__device__ int   g_mcur[NN];
__device__ int   g_mlist[NN];

// ---------------- kernels ----------------

__global__ void k_copy_edges0(const int* __restrict__ ei) {
    int e = blockIdx.x*blockDim.x + threadIdx.x;
    if (e >= EE) return;
    int s = ei[2*e], d = ei[2*e+1];
    g_esrc[0][e] = s;
    g_edst[0][e] = d;
    g_eew[0][e]  = 1.0f;
    atomicAdd(&g_cnt[d], 1);
}

// generic block scan: outx = within-block exclusive; g_bsum[b] = block total
__global__ void k_scanA(const int* __restrict__ in, int* __restrict__ outx) {
    __shared__ int sh[256];
    int tx = threadIdx.x;
    int v = blockIdx.x*256 + tx;
    int c = (v < NN) ? in[v] : 0;
    sh[tx] = c; __syncthreads();
    int val = c;
    for (int o = 1; o < 256; o <<= 1) {
        int y = (tx >= o) ? sh[tx-o] : 0;
        __syncthreads();
        val += y; sh[tx] = val;
        __syncthreads();
    }
    if (v < NN) outx[v] = val - c;
    if (tx == 255) g_bsum[blockIdx.x] = val;
}

__global__ void k_scan2() {
    __shared__ int sh[256];
    int tx = threadIdx.x;
    int c = (tx < NB) ? g_bsum[tx] : 0;
    sh[tx] = c; __syncthreads();
    int val = c;
    for (int o = 1; o < 256; o <<= 1) {
        int y = (tx >= o) ? sh[tx-o] : 0;
        __syncthreads();
        val += y; sh[tx] = val;
        __syncthreads();
    }
    g_boff[tx] = val - c;
}

__global__ void k_scan3(int t) {
    int v = blockIdx.x*blockDim.x + threadIdx.x;
    if (v >= NN) return;
    int c = g_cnt[v];
    int o = g_coff[t][v] + g_boff[v >> 8];
    g_coff[t][v] = o;
    g_wcur[v]    = o;
    g_ccnt[t][v] = c;
    g_dinv[t][v] = rsqrtf(2.0f + (float)c);
}

__global__ void k_fill(int t) {
    int e = blockIdx.x*blockDim.x + threadIdx.x;
    if (e >= EE) return;
    float w = g_eew[t][e];
    if (w <= 0.0f) return;
    int s = g_esrc[t][e], d = g_edst[t][e];
    int pos = atomicAdd(&g_wcur[d], 1);
    g_csrc[t][pos]  = s;
    g_cnorm[t][pos] = w * g_dinv[t][s] * g_dinv[t][d];
}

// unified 128x128-tile GEMM (kin=128). L<0: dense; L>=0: rows from g_act[L].
// applyScale: multiply row by pooled cluster weight (ssum/scnt) at load.
__global__ void __launch_bounds__(256) k_gemmT(const float* __restrict__ X,
                                               const float* __restrict__ W,
                                               float* __restrict__ out, int L,
                                               int applyScale) {
    __shared__ float Xs[32][132];
    __shared__ float Ws[32][128];
    __shared__ int rows[128];
    __shared__ float rwS[128];
    int count = (L >= 0) ? g_nact[L] : NN;
    int row0 = blockIdx.x * 128;
    if (row0 >= count) return;
    int tid = threadIdx.x;
    if (tid < 128) {
        int rr = row0 + tid;
        int row = (rr < count) ? ((L >= 0) ? g_act[L][rr] : rr) : -1;
        rows[tid] = row;
        float wv = 1.0f;
        if (applyScale && row >= 0) {
            float c = g_scnt[row];
            wv = (c > 0.0f) ? g_ssum[row] / fmaxf(c, 1.0f) : 1.0f;
        }
        rwS[tid] = wv;
    }
    __syncthreads();
    int cid = tid & 31;
    int rid = tid >> 5;
    float acc[16][4];
#pragma unroll
    for (int r = 0; r < 16; r++) { acc[r][0]=0.f; acc[r][1]=0.f; acc[r][2]=0.f; acc[r][3]=0.f; }
    for (int k0 = 0; k0 < HD; k0 += 32) {
        for (int i = tid; i < 128*8; i += 256) {
            int r = i >> 3, q = i & 7;
            int row = rows[r];
            float4 v = make_float4(0.f,0.f,0.f,0.f);
            if (row >= 0) {
                v = *(const float4*)&X[(size_t)row*HD + k0 + q*4];
                float wv = rwS[r];
                v.x *= wv; v.y *= wv; v.z *= wv; v.w *= wv;
            }
            Xs[q*4+0][r] = v.x; Xs[q*4+1][r] = v.y;
            Xs[q*4+2][r] = v.z; Xs[q*4+3][r] = v.w;
        }
        for (int i = tid; i < 32*128; i += 256) {
            int kk = i >> 7, c = i & 127;
            Ws[kk][c] = W[(size_t)(k0+kk)*HD + c];
        }
        __syncthreads();
#pragma unroll
        for (int kk = 0; kk < 32; kk++) {
            float4 w = *(const float4*)&Ws[kk][cid*4];
#pragma unroll
            for (int r = 0; r < 16; r++) {
                float xr = Xs[kk][rid + 8*r];
                acc[r][0] += xr*w.x; acc[r][1] += xr*w.y;
                acc[r][2] += xr*w.z; acc[r][3] += xr*w.w;
            }
        }
        __syncthreads();
    }
#pragma unroll
    for (int r = 0; r < 16; r++) {
        int row = rows[rid + 8*r];
        if (row >= 0)
            *(float4*)&out[(size_t)row*HD + cid*4] = make_float4(acc[r][0],acc[r][1],acc[r][2],acc[r][3]);
    }
}

// CSR gather conv
__global__ void k_conv_gather(int t, const float* __restrict__ b,
                              float* __restrict__ out, int dorelu) {
    int gt = blockIdx.x*blockDim.x + threadIdx.x;
    int v = gt >> 5, lane = gt & 31;
    if (v >= NN) return;
    int off = g_coff[t][v], n = g_ccnt[t][v];
    float4 acc = make_float4(0.f,0.f,0.f,0.f);
    for (int i = 0; i < n; i++) {
        int s   = g_csrc[t][off+i];
        float nm = g_cnorm[t][off+i];
        float4 xv = ((const float4*)(g_xw + (size_t)s*HD))[lane];
        acc.x += xv.x*nm; acc.y += xv.y*nm; acc.z += xv.z*nm; acc.w += xv.w*nm;
    }
    float dv = g_dinv[t][v];
    float sc = 2.0f*dv*dv;
    float4 xs = ((const float4*)(g_xw + (size_t)v*HD))[lane];
    float4 bb = ((const float4*)b)[lane];
    float4 o;
    o.x = acc.x + sc*xs.x + bb.x;
    o.y = acc.y + sc*xs.y + bb.y;
    o.z = acc.z + sc*xs.z + bb.z;
    o.w = acc.w + sc*xs.w + bb.w;
    if (dorelu) {
        o.x = fmaxf(o.x,0.f); o.y = fmaxf(o.y,0.f);
        o.z = fmaxf(o.z,0.f); o.w = fmaxf(o.w,0.f);
    }
    ((float4*)(out + (size_t)v*HD))[lane] = o;
}

__global__ void k_proj(const float* __restrict__ x, const float* __restrict__ Wp) {
    int gt = blockIdx.x*blockDim.x + threadIdx.x;
    int n = gt >> 5, lane = gt & 31;
    if (n >= NN) return;
    float4 xv = ((const float4*)(x + (size_t)n*HD))[lane];
    float4 w1 = ((const float4*)Wp)[lane];
    float4 w2 = ((const float4*)(Wp + HD))[lane];
    float a = xv.x*w1.x + xv.y*w1.y + xv.z*w1.z + xv.w*w1.w;
    float b = xv.x*w2.x + xv.y*w2.y + xv.z*w2.z + xv.w*w2.w;
#pragma unroll
    for (int o = 16; o > 0; o >>= 1) {
        a += __shfl_xor_sync(FULLMASK, a, o);
        b += __shfl_xor_sync(FULLMASK, b, o);
    }
    if (lane == 0) { g_p1[n] = a; g_p2[n] = b; g_parent[n] = n; }
}

__device__ __forceinline__ int uf_find(int x) {
    volatile int* P = g_parent;
    while (true) {
        int p = P[x];
        if (p == x) return x;
        int gp = P[p];
        if (gp == p) return p;
        P[x] = gp;
        x = gp;
    }
}

__global__ void k_score_union(int t, const float* __restrict__ bp) {
    int e = blockIdx.x*blockDim.x + threadIdx.x;
    if (e >= EE) return;
    float w = g_eew[t][e];
    int s = g_esrc[t][e], d = g_edst[t][e];
    float z = g_p1[s] + g_p2[d] + bp[0];
    float sc = 1.0f / (1.0f + expf(-z));
    bool sel = (w > 0.0f) && (s != d) && (sc > 0.5f);
    g_s[e] = sel ? sc : 0.0f;
    if (!sel) return;
    int ru = uf_find(s);
    int rv = uf_find(d);
    while (ru != rv) {
        if (ru < rv) { int tt = ru; ru = rv; rv = tt; }
        int old = atomicCAS(&g_parent[ru], ru, rv);
        if (old == ru) break;
        ru = uf_find(old);
        rv = uf_find(rv);
    }
}

// flatten + realm-restricted active append
__global__ void k_flatten(int L) {
    int v = blockIdx.x*blockDim.x + threadIdx.x;
    if (v >= NN) return;
    int r = uf_find(v);
    g_cl[L][v] = r;
    g_ssum[v] = 0.0f;
    g_scnt[v] = 0.0f;
    bool realm = (L == 0) ? true : (g_isact[L-1][v] != 0);
    unsigned char a = 0;
    if (realm && r == v) {
        int p = atomicAdd(&g_nact[L], 1);
        g_act[L][p] = v;
        a = 1;
    }
    g_isact[L][v] = a;
}

// fused: seg + relabel/dedup + next-level degree count
__global__ void k_seg_relabel(int tin, int tout, int L) {
    int e = blockIdx.x*blockDim.x + threadIdx.x;
    int lane = threadIdx.x & 31;
    int ns = 0, nd = 0; float nw = 0.0f;
    float s = 0.0f; int c = -1;
    if (e < EE) {
        float w = g_eew[tin][e];
        if (w > 0.0f) {
            int a = g_cl[L][g_esrc[tin][e]];
            int b = g_cl[L][g_edst[tin][e]];
            float sv = g_s[e];
            if (sv > 0.0f) { s = sv; c = a; }
            if (a != b) {
                unsigned key = (unsigned)a * (unsigned)NN + (unsigned)b;
                unsigned h = (unsigned)(((unsigned long long)key * 2654435761u) >> 11) & (HSZ-1);
                while (true) {
                    unsigned old = atomicCAS(&g_htab[h], 0xFFFFFFFFu, key);
                    if (old == 0xFFFFFFFFu) {
                        ns = a; nd = b; nw = 1.0f;
                        atomicAdd(&g_cnt[b], 1);
                        break;
                    }
                    if (old == key) break;
                    h = (h + 1) & (HSZ-1);
                }
            }
        }
        g_esrc[tout][e] = ns; g_edst[tout][e] = nd; g_eew[tout][e] = nw;
    }
    unsigned m = __match_any_sync(FULLMASK, c);
    int leader = __ffs(m) - 1;
    float tot = 0.0f;
#pragma unroll
    for (int j = 0; j < 32; j++) {
        float os = __shfl_sync(FULLMASK, s, j);
        int   oc = __shfl_sync(FULLMASK, c, j);
        if (lane == leader && c >= 0 && oc == c) tot += os;
    }
    if (lane == leader && c >= 0) {
        atomicAdd(&g_ssum[c], tot);
        atomicAdd(&g_scnt[c], (float)__popc(m));
    }
}

// ---- counting-sort pooling ----
__global__ void k_mcnt(int L) {
    int v = blockIdx.x*blockDim.x + threadIdx.x;
    int lane = threadIdx.x & 31;
    int c = (v < NN) ? g_cl[L][v] : -1;
    unsigned m = __match_any_sync(FULLMASK, c);
    int leader = __ffs(m) - 1;
    if (lane == leader && c >= 0) atomicAdd(&g_mcnt[c], __popc(m));
}

__global__ void k_mscan3() {
    int v = blockIdx.x*blockDim.x + threadIdx.x;
    if (v >= NN) return;
    int o = g_moff[v] + g_boff[v >> 8];
    g_moff[v] = o;
    g_mcur[v] = o;
}

__global__ void k_mfill(int L) {
    int v = blockIdx.x*blockDim.x + threadIdx.x;
    int lane = threadIdx.x & 31;
    int c = (v < NN) ? g_cl[L][v] : -1;
    unsigned m = __match_any_sync(FULLMASK, c);
    int leader = __ffs(m) - 1;
    int rank = __popc(m & ((1u << lane) - 1u));
    int base = 0;
    if (lane == leader && c >= 0) base = atomicAdd(&g_mcur[c], __popc(m));
    base = __shfl_sync(FULLMASK, base, leader);
    if (c >= 0) g_mlist[base + rank] = v;
}

// block per 128-member chunk of mlist; uniform-cluster fast path
__global__ void __launch_bounds__(256) k_poolacc(int L, const float* __restrict__ x,
                                                 float* __restrict__ xn) {
    int chunk0 = blockIdx.x * 128;
    if (chunk0 >= NN) return;
    int n = NN - chunk0; if (n > 128) n = 128;
    int tid = threadIdx.x;
    int f = tid & 127, half = tid >> 7;
    __shared__ float acc[2][128];
    __shared__ int c0s, unif;
    if (tid == 0) {
        int ca = g_cl[L][g_mlist[chunk0]];
        int cb = g_cl[L][g_mlist[chunk0 + n - 1]];
        c0s = ca; unif = (ca == cb);
    }
    __syncthreads();
    if (unif) {
        float a = 0.0f;
        for (int j = half; j < n; j += 2)
            a += x[(size_t)g_mlist[chunk0 + j]*HD + f];
        acc[half][f] = a;
        __syncthreads();
        if (half == 0)
            atomicAdd(&xn[(size_t)c0s*HD + f], acc[0][f] + acc[1][f]);
    } else {
        int lane4 = tid & 31;
        for (int j = tid >> 5; j < n; j += 8) {
            int mv = g_mlist[chunk0 + j];
            int c = g_cl[L][mv];
            float4 val = ((const float4*)(x + (size_t)mv*HD))[lane4];
            atomicAdd(((float4*)(xn + (size_t)c*HD)) + lane4, val);
        }
    }
}

__global__ void k_addg(int L) {
    int i = blockIdx.x*blockDim.x + threadIdx.x;
    if (i >= NN*32) return;
    int v = i >> 5, f4 = i & 31;
    float4 y = ((const float4*)(g_yb + (size_t)g_cl[L][v]*HD))[f4];
    float4* o = ((float4*)(g_xw + (size_t)v*HD)) + f4;
    float4 x = *o;
    x.x += y.x; x.y += y.y; x.z += y.z; x.w += y.w;
    *o = x;
}

__global__ void k_yb2(const float* __restrict__ xup, const float* __restrict__ Wu2c) {
    int gt = blockIdx.x*blockDim.x + threadIdx.x;
    int j = gt >> 5, lane = gt & 31;
    if (j >= g_nact[0]) return;
    int row = g_act[0][j];
    float4 xv = ((const float4*)(xup + (size_t)row*HD))[lane];
    float4 wv = ((const float4*)Wu2c)[lane];
    float a = xv.x*wv.x + xv.y*wv.y + xv.z*wv.z + xv.w*wv.w;
#pragma unroll
    for (int o = 16; o > 0; o >>= 1) a += __shfl_xor_sync(FULLMASK, a, o);
    if (lane == 0) g_p1[row] = a;
}

__global__ void k_xw1(const float* __restrict__ m0, const float* __restrict__ xin,
                      const float* __restrict__ Wu2) {
    int gt = blockIdx.x*blockDim.x + threadIdx.x;
    int v = gt >> 5, lane = gt & 31;
    if (v >= NN) return;
    float4 x1 = ((const float4*)(m0  + (size_t)v*HD))[lane];
    float4 x2 = ((const float4*)(xin + (size_t)v*HD))[lane];
    float4 w1 = ((const float4*)Wu2)[lane];
    float4 w2 = ((const float4*)(Wu2 + HD))[lane];
    float a = x1.x*w1.x + x1.y*w1.y + x1.z*w1.z + x1.w*w1.w
            + x2.x*w2.x + x2.y*w2.y + x2.z*w2.z + x2.w*w2.w;
#pragma unroll
    for (int o = 16; o > 0; o >>= 1) a += __shfl_xor_sync(FULLMASK, a, o);
    if (lane == 0) g_xw1[v] = a + g_p1[g_cl[0][v]];
}

__global__ void k_conv1(const float* __restrict__ bu, float* __restrict__ out) {
    int gt = blockIdx.x*blockDim.x + threadIdx.x;
    int v = gt >> 5, lane = gt & 31;
    if (v >= NN) return;
    int off = g_coff[0][v], n = g_ccnt[0][v];
    float acc = 0.0f;
    for (int i = lane; i < n; i += 32)
        acc += g_xw1[g_csrc[0][off+i]] * g_cnorm[0][off+i];
#pragma unroll
    for (int o = 16; o > 0; o >>= 1) acc += __shfl_xor_sync(FULLMASK, acc, o);
    if (lane == 0) {
        float dv = g_dinv[0][v];
        float z = acc + 2.0f*dv*dv*g_xw1[v] + bu[0];
        out[v] = 1.0f / (1.0f + expf(-z));
    }
}

// ---------------- host orchestration ----------------

extern "C" void kernel_launch(void* const* d_in, const int* in_sizes, int n_in,
                              void* d_out, int out_size) {
    (void)in_sizes; (void)n_in; (void)out_size;
    const float* x_in = (const float*)d_in[0];
    const int*   ei   = (const int*)d_in[1];
    const float* Wd[4] = {(const float*)d_in[3],(const float*)d_in[5],(const float*)d_in[7],(const float*)d_in[9]};
    const float* bd[4] = {(const float*)d_in[4],(const float*)d_in[6],(const float*)d_in[8],(const float*)d_in[10]};
    const float* Wp[3] = {(const float*)d_in[11],(const float*)d_in[13],(const float*)d_in[15]};
    const float* bp[3] = {(const float*)d_in[12],(const float*)d_in[14],(const float*)d_in[16]};
    const float* Wu[3] = {(const float*)d_in[17],(const float*)d_in[19],(const float*)d_in[21]};
    const float* bu[3] = {(const float*)d_in[18],(const float*)d_in[20],(const float*)d_in[22]};
    float* out = (float*)d_out;

    void* pv;
    float *p_xa, *p_xb, *p_cv, *p_m0, *p_m1, *p_m2, *p_xw, *p_yb;
    int *p_cnt, *p_nact, *p_mcnt, *p_moff; unsigned *p_htab;
    cudaGetSymbolAddress(&pv, g_xa);   p_xa   = (float*)pv;
    cudaGetSymbolAddress(&pv, g_xb);   p_xb   = (float*)pv;
    cudaGetSymbolAddress(&pv, g_cv);   p_cv   = (float*)pv;
    cudaGetSymbolAddress(&pv, g_m0);   p_m0   = (float*)pv;
    cudaGetSymbolAddress(&pv, g_m1);   p_m1   = (float*)pv;
    cudaGetSymbolAddress(&pv, g_m2);   p_m2   = (float*)pv;
    cudaGetSymbolAddress(&pv, g_xw);   p_xw   = (float*)pv;
    cudaGetSymbolAddress(&pv, g_yb);   p_yb   = (float*)pv;
    cudaGetSymbolAddress(&pv, g_cnt);  p_cnt  = (int*)pv;
    cudaGetSymbolAddress(&pv, g_nact); p_nact = (int*)pv;
    cudaGetSymbolAddress(&pv, g_mcnt); p_mcnt = (int*)pv;
    cudaGetSymbolAddress(&pv, g_moff); p_moff = (int*)pv;
    cudaGetSymbolAddress(&pv, g_htab); p_htab = (unsigned*)pv;

    const int gN  = (NN + NT - 1) / NT;
    const int gN4 = (NN*32 + NT - 1) / NT;
    const int gE  = (EE + NT - 1) / NT;
    const int gNw = (NN*32 + NT - 1) / NT;
    const int gG  = (NN + 127) / 128;

    cudaMemsetAsync(p_cnt, 0, NN*sizeof(int));
    cudaMemsetAsync(p_nact, 0, 3*sizeof(int));
    k_copy_edges0<<<gE, NT>>>(ei);

    const float* Xin[3]  = { x_in, p_xa, p_xb };
    float*       memb[3] = { p_m0, p_m1, p_m2 };
    float*       xout[3] = { p_xa, p_xb, p_xa };
    int*         coffp;
    cudaGetSymbolAddress(&pv, g_coff); coffp = (int*)pv;

    for (int i = 0; i < 3; i++) {
        int t = i;
        k_scanA<<<NB, 256>>>(p_cnt, coffp + t*NN);
        k_scan2<<<1, 256>>>();
        if (i == 0) {
            k_gemmT<<<gG, 256>>>(x_in, Wd[0], p_xw, -1, 0);
        } else {
            cudaMemsetAsync(p_xw, 0, (size_t)NN*HD*sizeof(float));
            k_gemmT<<<gG, 256>>>(Xin[i], Wd[i], p_xw, i-1, 1);
        }
        k_scan3<<<gN, NT>>>(t);
        k_fill<<<gE, NT>>>(t);
        k_conv_gather<<<gNw, NT>>>(t, bd[i], memb[i], 1);
        // pooling
        k_proj<<<gNw, NT>>>(memb[i], Wp[i]);
        k_score_union<<<gE, NT>>>(t, bp[i]);
        k_flatten<<<gN, NT>>>(i);
        cudaMemsetAsync(xout[i], 0, (size_t)NN*HD*sizeof(float));
        cudaMemsetAsync(p_htab, 0xFF, HSZ*sizeof(unsigned));
        cudaMemsetAsync(p_cnt, 0, NN*sizeof(int));
        cudaMemsetAsync(p_mcnt, 0, NN*sizeof(int));
        k_seg_relabel<<<gE, NT>>>(t, t+1, i);
        // counting-sort pooling
        k_mcnt<<<gN, NT>>>(i);
        k_scanA<<<NB, 256>>>(p_mcnt, p_moff);
        k_scan2<<<1, 256>>>();
        k_mscan3<<<gN, NT>>>();
        k_mfill<<<gN, NT>>>(i);
        k_poolacc<<<gG, 256>>>(i, memb[i], xout[i]);
    }

    // ---- bottom conv (topology 3) ----
    k_scanA<<<NB, 256>>>(p_cnt, coffp + 3*NN);
    k_scan2<<<1, 256>>>();
    cudaMemsetAsync(p_xw, 0, (size_t)NN*HD*sizeof(float));
    k_gemmT<<<gG, 256>>>(p_xa, Wd[3], p_xw, 2, 1);
    k_scan3<<<gN, NT>>>(3);
    k_fill<<<gE, NT>>>(3);
    k_conv_gather<<<gNw, NT>>>(3, bd[3], p_cv, 0);

    // ---- UP 0 : level L=2, topology 2 ----
    k_gemmT<<<gG, 256>>>(p_m2, Wu[0], p_xw, -1, 0);
    k_gemmT<<<gG, 256>>>(p_cv, Wu[0] + 128*HD, p_yb, 2, 0);
    k_addg<<<gN4, NT>>>(2);
    k_conv_gather<<<gNw, NT>>>(2, bu[0], p_xa, 1);

    // ---- UP 1 : level L=1, topology 1 ----
    k_gemmT<<<gG, 256>>>(p_m1, Wu[1], p_xw, -1, 0);
    k_gemmT<<<gG, 256>>>(p_xa, Wu[1] + 128*HD, p_yb, 1, 0);
    k_addg<<<gN4, NT>>>(1);
    k_conv_gather<<<gNw, NT>>>(1, bu[1], p_xb, 1);

    // ---- UP 2 : level L=0, topology 0, output dim 1 ----
    k_yb2<<<gNw, NT>>>(p_xb, Wu[2] + 256);
    k_xw1<<<gNw, NT>>>(p_m0, x_in, Wu[2]);
    k_conv1<<<gNw, NT>>>(bu[2], out);
}

// round 8
// speedup vs baseline: 1.5900x; 1.0585x over previous
#include <cuda_runtime.h>
#include <math.h>

#define NN 50000
#define EE 800000
#define HD 128
#define HSZ (1u<<21)
#define NT 256
#define FULLMASK 0xffffffffu
#define NB 196   // (NN+255)/256

// ---------------- static device scratch ----------------
__device__ float g_xw[NN*HD];
__device__ float g_cv[NN*HD];
__device__ float g_xa[NN*HD];
__device__ float g_xb[NN*HD];
__device__ float g_m0[NN*HD];
__device__ float g_m1[NN*HD];
__device__ float g_m2[NN*HD];
__device__ float g_yb[NN*HD];
__device__ float g_p1[NN];
__device__ float g_p2[NN];
__device__ float g_dinv[4][NN];
__device__ float g_ssum[NN];
__device__ float g_scnt[NN];
__device__ int   g_parent[NN];
__device__ int   g_cl[3][NN];
__device__ int   g_act[3][NN];
__device__ int   g_nact[3];
__device__ unsigned char g_isact[3][NN];
__device__ int   g_esrc[4][EE];
__device__ int   g_edst[4][EE];
__device__ int   g_ne[4];          // compacted edge counts (levels >= 1)
__device__ unsigned g_htab[HSZ];
__device__ float g_xw1[NN];
__device__ int   g_coff[4][NN];
__device__ int   g_ccnt[4][NN];
__device__ int   g_csrc[4][EE];
__device__ float g_cnorm[4][EE];
__device__ int   g_cnt[NN];
__device__ int   g_wcur[NN];
__device__ int   g_bsum[256];
__device__ int   g_boff[256];
// member sort for pooling
__device__ int   g_mcnt[NN];
__device__ int   g_moff[NN];
__device__ int   g_mcur[NN];
__device__ int   g_mlist[NN];

// ---------------- kernels ----------------

__global__ void k_copy_edges0(const int* __restrict__ ei) {
    int e = blockIdx.x*blockDim.x + threadIdx.x;
    if (e >= EE) return;
    int s = ei[2*e], d = ei[2*e+1];
    g_esrc[0][e] = s;
    g_edst[0][e] = d;
    atomicAdd(&g_cnt[d], 1);
}

// generic block scan: outx = within-block exclusive; g_bsum[b] = block total
__global__ void k_scanA(const int* __restrict__ in, int* __restrict__ outx) {
    __shared__ int sh[256];
    int tx = threadIdx.x;
    int v = blockIdx.x*256 + tx;
    int c = (v < NN) ? in[v] : 0;
    sh[tx] = c; __syncthreads();
    int val = c;
    for (int o = 1; o < 256; o <<= 1) {
        int y = (tx >= o) ? sh[tx-o] : 0;
        __syncthreads();
        val += y; sh[tx] = val;
        __syncthreads();
    }
    if (v < NN) outx[v] = val - c;
    if (tx == 255) g_bsum[blockIdx.x] = val;
}

__global__ void k_scan2() {
    __shared__ int sh[256];
    int tx = threadIdx.x;
    int c = (tx < NB) ? g_bsum[tx] : 0;
    sh[tx] = c; __syncthreads();
    int val = c;
    for (int o = 1; o < 256; o <<= 1) {
        int y = (tx >= o) ? sh[tx-o] : 0;
        __syncthreads();
        val += y; sh[tx] = val;
        __syncthreads();
    }
    g_boff[tx] = val - c;
}

__global__ void k_scan3(int t) {
    int v = blockIdx.x*blockDim.x + threadIdx.x;
    if (v >= NN) return;
    int c = g_cnt[v];
    int o = g_coff[t][v] + g_boff[v >> 8];
    g_coff[t][v] = o;
    g_wcur[v]    = o;
    g_ccnt[t][v] = c;
    g_dinv[t][v] = rsqrtf(2.0f + (float)c);
}

__global__ void k_fill(int t) {
    int e = blockIdx.x*blockDim.x + threadIdx.x;
    int cnt = (t == 0) ? EE : g_ne[t];
    if (e >= cnt) return;
    int s = g_esrc[t][e], d = g_edst[t][e];
    int pos = atomicAdd(&g_wcur[d], 1);
    g_csrc[t][pos]  = s;
    g_cnorm[t][pos] = g_dinv[t][s] * g_dinv[t][d];
}

// unified 128x128-tile GEMM (kin=128). L<0: dense; L>=0: rows from g_act[L].
__global__ void __launch_bounds__(256) k_gemmT(const float* __restrict__ X,
                                               const float* __restrict__ W,
                                               float* __restrict__ out, int L,
                                               int applyScale) {
    __shared__ float Xs[32][132];
    __shared__ float Ws[32][128];
    __shared__ int rows[128];
    __shared__ float rwS[128];
    int count = (L >= 0) ? g_nact[L] : NN;
    int row0 = blockIdx.x * 128;
    if (row0 >= count) return;
    int tid = threadIdx.x;
    if (tid < 128) {
        int rr = row0 + tid;
        int row = (rr < count) ? ((L >= 0) ? g_act[L][rr] : rr) : -1;
        rows[tid] = row;
        float wv = 1.0f;
        if (applyScale && row >= 0) {
            float c = g_scnt[row];
            wv = (c > 0.0f) ? g_ssum[row] / fmaxf(c, 1.0f) : 1.0f;
        }
        rwS[tid] = wv;
    }
    __syncthreads();
    int cid = tid & 31;
    int rid = tid >> 5;
    float acc[16][4];
#pragma unroll
    for (int r = 0; r < 16; r++) { acc[r][0]=0.f; acc[r][1]=0.f; acc[r][2]=0.f; acc[r][3]=0.f; }
    for (int k0 = 0; k0 < HD; k0 += 32) {
        for (int i = tid; i < 128*8; i += 256) {
            int r = i >> 3, q = i & 7;
            int row = rows[r];
            float4 v = make_float4(0.f,0.f,0.f,0.f);
            if (row >= 0) {
                v = *(const float4*)&X[(size_t)row*HD + k0 + q*4];
                float wv = rwS[r];
                v.x *= wv; v.y *= wv; v.z *= wv; v.w *= wv;
            }
            Xs[q*4+0][r] = v.x; Xs[q*4+1][r] = v.y;
            Xs[q*4+2][r] = v.z; Xs[q*4+3][r] = v.w;
        }
        for (int i = tid; i < 32*128; i += 256) {
            int kk = i >> 7, c = i & 127;
            Ws[kk][c] = W[(size_t)(k0+kk)*HD + c];
        }
        __syncthreads();
#pragma unroll
        for (int kk = 0; kk < 32; kk++) {
            float4 w = *(const float4*)&Ws[kk][cid*4];
#pragma unroll
            for (int r = 0; r < 16; r++) {
                float xr = Xs[kk][rid + 8*r];
                acc[r][0] += xr*w.x; acc[r][1] += xr*w.y;
                acc[r][2] += xr*w.z; acc[r][3] += xr*w.w;
            }
        }
        __syncthreads();
    }
#pragma unroll
    for (int r = 0; r < 16; r++) {
        int row = rows[rid + 8*r];
        if (row >= 0)
            *(float4*)&out[(size_t)row*HD + cid*4] = make_float4(acc[r][0],acc[r][1],acc[r][2],acc[r][3]);
    }
}

// CSR gather conv. Optional fused: yb-add via cluster indirection (up path),
// proj p1/p2 + parent init (down path).
__global__ void k_conv(int t, const float* __restrict__ b, float* __restrict__ out,
                       int dorelu, const float* __restrict__ Wp,
                       int useYb, const int* __restrict__ cl) {
    int gt = blockIdx.x*blockDim.x + threadIdx.x;
    int v = gt >> 5, lane = gt & 31;
    if (v >= NN) return;
    int off = g_coff[t][v], n = g_ccnt[t][v];
    float4 acc = make_float4(0.f,0.f,0.f,0.f);
    for (int i = 0; i < n; i++) {
        int s   = g_csrc[t][off+i];
        float nm = g_cnorm[t][off+i];
        float4 xv = ((const float4*)(g_xw + (size_t)s*HD))[lane];
        if (useYb) {
            float4 yv = ((const float4*)(g_yb + (size_t)cl[s]*HD))[lane];
            xv.x += yv.x; xv.y += yv.y; xv.z += yv.z; xv.w += yv.w;
        }
        acc.x += xv.x*nm; acc.y += xv.y*nm; acc.z += xv.z*nm; acc.w += xv.w*nm;
    }
    float dv = g_dinv[t][v];
    float sc = 2.0f*dv*dv;
    float4 xs = ((const float4*)(g_xw + (size_t)v*HD))[lane];
    if (useYb) {
        float4 yv = ((const float4*)(g_yb + (size_t)cl[v]*HD))[lane];
        xs.x += yv.x; xs.y += yv.y; xs.z += yv.z; xs.w += yv.w;
    }
    float4 bb = ((const float4*)b)[lane];
    float4 o;
    o.x = acc.x + sc*xs.x + bb.x;
    o.y = acc.y + sc*xs.y + bb.y;
    o.z = acc.z + sc*xs.z + bb.z;
    o.w = acc.w + sc*xs.w + bb.w;
    if (dorelu) {
        o.x = fmaxf(o.x,0.f); o.y = fmaxf(o.y,0.f);
        o.z = fmaxf(o.z,0.f); o.w = fmaxf(o.w,0.f);
    }
    ((float4*)(out + (size_t)v*HD))[lane] = o;
    if (Wp) {
        float4 w1 = ((const float4*)Wp)[lane];
        float4 w2 = ((const float4*)(Wp + HD))[lane];
        float a = o.x*w1.x + o.y*w1.y + o.z*w1.z + o.w*w1.w;
        float b2 = o.x*w2.x + o.y*w2.y + o.z*w2.z + o.w*w2.w;
#pragma unroll
        for (int q = 16; q > 0; q >>= 1) {
            a  += __shfl_xor_sync(FULLMASK, a, q);
            b2 += __shfl_xor_sync(FULLMASK, b2, q);
        }
        if (lane == 0) { g_p1[v] = a; g_p2[v] = b2; g_parent[v] = v; }
    }
}

__device__ __forceinline__ int uf_find(int x) {
    volatile int* P = g_parent;
    while (true) {
        int p = P[x];
        if (p == x) return x;
        int gp = P[p];
        if (gp == p) return p;
        P[x] = gp;
        x = gp;
    }
}

// sigma(z) > 0.5  <=>  z > 0 : no expf needed here
__global__ void k_score_union(int t, const float* __restrict__ bp) {
    int e = blockIdx.x*blockDim.x + threadIdx.x;
    int cnt = (t == 0) ? EE : g_ne[t];
    if (e >= cnt) return;
    int s = g_esrc[t][e], d = g_edst[t][e];
    float z = g_p1[s] + g_p2[d] + bp[0];
    if (s == d || z <= 0.0f) return;
    int ru = uf_find(s);
    int rv = uf_find(d);
    while (ru != rv) {
        if (ru < rv) { int tt = ru; ru = rv; rv = tt; }
        int old = atomicCAS(&g_parent[ru], ru, rv);
        if (old == ru) break;
        ru = uf_find(old);
        rv = uf_find(rv);
    }
}

// flatten + realm-restricted active append + zero counters for next phase
__global__ void k_flatten(int L) {
    int v = blockIdx.x*blockDim.x + threadIdx.x;
    if (v >= NN) return;
    int r = uf_find(v);
    g_cl[L][v] = r;
    g_ssum[v] = 0.0f;
    g_scnt[v] = 0.0f;
    g_cnt[v] = 0;
    g_mcnt[v] = 0;
    bool realm = (L == 0) ? true : (g_isact[L-1][v] != 0);
    unsigned char a = 0;
    if (realm && r == v) {
        int p = atomicAdd(&g_nact[L], 1);
        g_act[L][p] = v;
        a = 1;
    }
    g_isact[L][v] = a;
}

// fused: seg (score sums by cluster) + compacting relabel/dedup + next degree count
__global__ void k_seg_relabel(int tin, int L, const float* __restrict__ bp) {
    int e = blockIdx.x*blockDim.x + threadIdx.x;
    int lane = threadIdx.x & 31;
    int cnt = (tin == 0) ? EE : g_ne[tin];
    float sval = 0.0f; int c = -1;
    if (e < cnt) {
        int s = g_esrc[tin][e], d = g_edst[tin][e];
        int a = g_cl[L][s];
        int b = g_cl[L][d];
        float z = g_p1[s] + g_p2[d] + bp[0];
        if (s != d && z > 0.0f) {
            sval = 1.0f / (1.0f + expf(-z));
            c = a;      // selected edges are intra-cluster (a == b)
        }
        if (a != b) {
            unsigned key = (unsigned)a * (unsigned)NN + (unsigned)b;
            unsigned h = (unsigned)(((unsigned long long)key * 2654435761u) >> 11) & (HSZ-1);
            while (true) {
                unsigned old = atomicCAS(&g_htab[h], 0xFFFFFFFFu, key);
                if (old == 0xFFFFFFFFu) {
                    int pos = atomicAdd(&g_ne[tin+1], 1);
                    g_esrc[tin+1][pos] = a;
                    g_edst[tin+1][pos] = b;
                    atomicAdd(&g_cnt[b], 1);
                    break;
                }
                if (old == key) break;
                h = (h + 1) & (HSZ-1);
            }
        }
    }
    unsigned m = __match_any_sync(FULLMASK, c);
    int leader = __ffs(m) - 1;
    float tot = 0.0f;
#pragma unroll
    for (int j = 0; j < 32; j++) {
        float os = __shfl_sync(FULLMASK, sval, j);
        int   oc = __shfl_sync(FULLMASK, c, j);
        if (lane == leader && c >= 0 && oc == c) tot += os;
    }
    if (lane == leader && c >= 0) {
        atomicAdd(&g_ssum[c], tot);
        atomicAdd(&g_scnt[c], (float)__popc(m));
    }
}

// ---- counting-sort pooling ----
__global__ void k_mcnt(int L) {
    int v = blockIdx.x*blockDim.x + threadIdx.x;
    int lane = threadIdx.x & 31;
    int c = (v < NN) ? g_cl[L][v] : -1;
    unsigned m = __match_any_sync(FULLMASK, c);
    int leader = __ffs(m) - 1;
    if (lane == leader && c >= 0) atomicAdd(&g_mcnt[c], __popc(m));
}

__global__ void k_mscan3() {
    int v = blockIdx.x*blockDim.x + threadIdx.x;
    if (v >= NN) return;
    int o = g_moff[v] + g_boff[v >> 8];
    g_moff[v] = o;
    g_mcur[v] = o;
}

__global__ void k_mfill(int L) {
    int v = blockIdx.x*blockDim.x + threadIdx.x;
    int lane = threadIdx.x & 31;
    int c = (v < NN) ? g_cl[L][v] : -1;
    unsigned m = __match_any_sync(FULLMASK, c);
    int leader = __ffs(m) - 1;
    int rank = __popc(m & ((1u << lane) - 1u));
    int base = 0;
    if (lane == leader && c >= 0) base = atomicAdd(&g_mcur[c], __popc(m));
    base = __shfl_sync(FULLMASK, base, leader);
    if (c >= 0) g_mlist[base + rank] = v;
}

// block per 128-member chunk of mlist; uniform-cluster fast path
__global__ void __launch_bounds__(256) k_poolacc(int L, const float* __restrict__ x,
                                                 float* __restrict__ xn) {
    int chunk0 = blockIdx.x * 128;
    if (chunk0 >= NN) return;
    int n = NN - chunk0; if (n > 128) n = 128;
    int tid = threadIdx.x;
    int f = tid & 127, half = tid >> 7;
    __shared__ float acc[2][128];
    __shared__ int c0s, unif;
    if (tid == 0) {
        int ca = g_cl[L][g_mlist[chunk0]];
        int cb = g_cl[L][g_mlist[chunk0 + n - 1]];
        c0s = ca; unif = (ca == cb);
    }
    __syncthreads();
    if (unif) {
        float a = 0.0f;
        for (int j = half; j < n; j += 2)
            a += x[(size_t)g_mlist[chunk0 + j]*HD + f];
        acc[half][f] = a;
        __syncthreads();
        if (half == 0)
            atomicAdd(&xn[(size_t)c0s*HD + f], acc[0][f] + acc[1][f]);
    } else {
        int lane4 = tid & 31;
        for (int j = tid >> 5; j < n; j += 8) {
            int mv = g_mlist[chunk0 + j];
            int c = g_cl[L][mv];
            float4 val = ((const float4*)(x + (size_t)mv*HD))[lane4];
            atomicAdd(((float4*)(xn + (size_t)c*HD)) + lane4, val);
        }
    }
}

__global__ void k_yb2(const float* __restrict__ xup, const float* __restrict__ Wu2c) {
    int gt = blockIdx.x*blockDim.x + threadIdx.x;
    int j = gt >> 5, lane = gt & 31;
    if (j >= g_nact[0]) return;
    int row = g_act[0][j];
    float4 xv = ((const float4*)(xup + (size_t)row*HD))[lane];
    float4 wv = ((const float4*)Wu2c)[lane];
    float a = xv.x*wv.x + xv.y*wv.y + xv.z*wv.z + xv.w*wv.w;
#pragma unroll
    for (int o = 16; o > 0; o >>= 1) a += __shfl_xor_sync(FULLMASK, a, o);
    if (lane == 0) g_p1[row] = a;
}

__global__ void k_xw1(const float* __restrict__ m0, const float* __restrict__ xin,
                      const float* __restrict__ Wu2) {
    int gt = blockIdx.x*blockDim.x + threadIdx.x;
    int v = gt >> 5, lane = gt & 31;
    if (v >= NN) return;
    float4 x1 = ((const float4*)(m0  + (size_t)v*HD))[lane];
    float4 x2 = ((const float4*)(xin + (size_t)v*HD))[lane];
    float4 w1 = ((const float4*)Wu2)[lane];
    float4 w2 = ((const float4*)(Wu2 + HD))[lane];
    float a = x1.x*w1.x + x1.y*w1.y + x1.z*w1.z + x1.w*w1.w
            + x2.x*w2.x + x2.y*w2.y + x2.z*w2.z + x2.w*w2.w;
#pragma unroll
    for (int o = 16; o > 0; o >>= 1) a += __shfl_xor_sync(FULLMASK, a, o);
    if (lane == 0) g_xw1[v] = a + g_p1[g_cl[0][v]];
}

__global__ void k_conv1(const float* __restrict__ bu, float* __restrict__ out) {
    int gt = blockIdx.x*blockDim.x + threadIdx.x;
    int v = gt >> 5, lane = gt & 31;
    if (v >= NN) return;
    int off = g_coff[0][v], n = g_ccnt[0][v];
    float acc = 0.0f;
    for (int i = lane; i < n; i += 32)
        acc += g_xw1[g_csrc[0][off+i]] * g_cnorm[0][off+i];
#pragma unroll
    for (int o = 16; o > 0; o >>= 1) acc += __shfl_xor_sync(FULLMASK, acc, o);
    if (lane == 0) {
        float dv = g_dinv[0][v];
        float z = acc + 2.0f*dv*dv*g_xw1[v] + bu[0];
        out[v] = 1.0f / (1.0f + expf(-z));
    }
}

// ---------------- host orchestration ----------------

extern "C" void kernel_launch(void* const* d_in, const int* in_sizes, int n_in,
                              void* d_out, int out_size) {
    (void)in_sizes; (void)n_in; (void)out_size;
    const float* x_in = (const float*)d_in[0];
    const int*   ei   = (const int*)d_in[1];
    const float* Wd[4] = {(const float*)d_in[3],(const float*)d_in[5],(const float*)d_in[7],(const float*)d_in[9]};
    const float* bd[4] = {(const float*)d_in[4],(const float*)d_in[6],(const float*)d_in[8],(const float*)d_in[10]};
    const float* Wp[3] = {(const float*)d_in[11],(const float*)d_in[13],(const float*)d_in[15]};
    const float* bp[3] = {(const float*)d_in[12],(const float*)d_in[14],(const float*)d_in[16]};
    const float* Wu[3] = {(const float*)d_in[17],(const float*)d_in[19],(const float*)d_in[21]};
    const float* bu[3] = {(const float*)d_in[18],(const float*)d_in[20],(const float*)d_in[22]};
    float* out = (float*)d_out;

    void* pv;
    float *p_xa, *p_xb, *p_cv, *p_m0, *p_m1, *p_m2, *p_xw, *p_yb;
    int *p_cnt, *p_nact, *p_ne, *p_mcnt, *p_moff, *p_cl; unsigned *p_htab;
    cudaGetSymbolAddress(&pv, g_xa);   p_xa   = (float*)pv;
    cudaGetSymbolAddress(&pv, g_xb);   p_xb   = (float*)pv;
    cudaGetSymbolAddress(&pv, g_cv);   p_cv   = (float*)pv;
    cudaGetSymbolAddress(&pv, g_m0);   p_m0   = (float*)pv;
    cudaGetSymbolAddress(&pv, g_m1);   p_m1   = (float*)pv;
    cudaGetSymbolAddress(&pv, g_m2);   p_m2   = (float*)pv;
    cudaGetSymbolAddress(&pv, g_xw);   p_xw   = (float*)pv;
    cudaGetSymbolAddress(&pv, g_yb);   p_yb   = (float*)pv;
    cudaGetSymbolAddress(&pv, g_cnt);  p_cnt  = (int*)pv;
    cudaGetSymbolAddress(&pv, g_nact); p_nact = (int*)pv;
    cudaGetSymbolAddress(&pv, g_ne);   p_ne   = (int*)pv;
    cudaGetSymbolAddress(&pv, g_mcnt); p_mcnt = (int*)pv;
    cudaGetSymbolAddress(&pv, g_moff); p_moff = (int*)pv;
    cudaGetSymbolAddress(&pv, g_cl);   p_cl   = (int*)pv;
    cudaGetSymbolAddress(&pv, g_htab); p_htab = (unsigned*)pv;
    int* coffp;
    cudaGetSymbolAddress(&pv, g_coff); coffp = (int*)pv;

    const int gN  = (NN + NT - 1) / NT;
    const int gE  = (EE + NT - 1) / NT;
    const int gNw = (NN*32 + NT - 1) / NT;
    const int gG  = (NN + 127) / 128;

    cudaMemsetAsync(p_cnt, 0, NN*sizeof(int));
    cudaMemsetAsync(p_nact, 0, 3*sizeof(int));
    cudaMemsetAsync(p_ne, 0, 4*sizeof(int));
    k_copy_edges0<<<gE, NT>>>(ei);

    const float* Xin[3]  = { x_in, p_xa, p_xb };
    float*       memb[3] = { p_m0, p_m1, p_m2 };
    float*       xout[3] = { p_xa, p_xb, p_xa };

    for (int i = 0; i < 3; i++) {
        int t = i;
        k_scanA<<<NB, 256>>>(p_cnt, coffp + t*NN);
        k_scan2<<<1, 256>>>();
        if (i == 0) k_gemmT<<<gG, 256>>>(x_in, Wd[0], p_xw, -1, 0);
        else        k_gemmT<<<gG, 256>>>(Xin[i], Wd[i], p_xw, i-1, 1);
        k_scan3<<<gN, NT>>>(t);
        k_fill<<<gE, NT>>>(t);
        k_conv<<<gNw, NT>>>(t, bd[i], memb[i], 1, Wp[i], 0, (const int*)0);
        k_score_union<<<gE, NT>>>(t, bp[i]);
        k_flatten<<<gN, NT>>>(i);
        cudaMemsetAsync(xout[i], 0, (size_t)NN*HD*sizeof(float));
        cudaMemsetAsync(p_htab, 0xFF, HSZ*sizeof(unsigned));
        k_seg_relabel<<<gE, NT>>>(t, i, bp[i]);
        // counting-sort pooling
        k_mcnt<<<gN, NT>>>(i);
        k_scanA<<<NB, 256>>>(p_mcnt, p_moff);
        k_scan2<<<1, 256>>>();
        k_mscan3<<<gN, NT>>>();
        k_mfill<<<gN, NT>>>(i);
        k_poolacc<<<gG, 256>>>(i, memb[i], xout[i]);
    }

    // ---- bottom conv (topology 3) ----
    k_scanA<<<NB, 256>>>(p_cnt, coffp + 3*NN);
    k_scan2<<<1, 256>>>();
    k_gemmT<<<gG, 256>>>(p_xa, Wd[3], p_xw, 2, 1);
    k_scan3<<<gN, NT>>>(3);
    k_fill<<<gE, NT>>>(3);
    k_conv<<<gNw, NT>>>(3, bd[3], p_cv, 0, (const float*)0, 0, (const int*)0);

    // ---- UP 0 : level L=2, topology 2 ----
    k_gemmT<<<gG, 256>>>(p_m2, Wu[0], p_xw, -1, 0);
    k_gemmT<<<gG, 256>>>(p_cv, Wu[0] + 128*HD, p_yb, 2, 0);
    k_conv<<<gNw, NT>>>(2, bu[0], p_xa, 1, (const float*)0, 1, p_cl + 2*NN);

    // ---- UP 1 : level L=1, topology 1 ----
    k_gemmT<<<gG, 256>>>(p_m1, Wu[1], p_xw, -1, 0);
    k_gemmT<<<gG, 256>>>(p_xa, Wu[1] + 128*HD, p_yb, 1, 0);
    k_conv<<<gNw, NT>>>(1, bu[1], p_xb, 1, (const float*)0, 1, p_cl + 1*NN);

    // ---- UP 2 : level L=0, topology 0, output dim 1 ----
    k_yb2<<<gNw, NT>>>(p_xb, Wu[2] + 256);
    k_xw1<<<gNw, NT>>>(p_m0, x_in, Wu[2]);
    k_conv1<<<gNw, NT>>>(bu[2], out);
}

// round 9
// speedup vs baseline: 1.8300x; 1.1509x over previous
#include <cuda_runtime.h>
#include <math.h>

#define NN 50000
#define EE 800000
#define HD 128
#define HSZ (1u<<20)
#define NT 256
#define FULLMASK 0xffffffffu
#define NB 196   // (NN+255)/256
#define NBW 512  // blocks for warp-loop kernels (4096 warps)

#define MI_NACT 0   // misc[0..2]  = nact[L]
#define MI_NE   4   // misc[4..7]  = compacted edge counts
// ---------------- static device scratch ----------------
__device__ float g_xw[NN*HD];
__device__ float g_cv[NN*HD];
__device__ float g_xa[NN*HD];
__device__ float g_xb[NN*HD];
__device__ float g_m0[NN*HD];
__device__ float g_m1[NN*HD];
__device__ float g_m2[NN*HD];
__device__ float g_yb[NN*HD];
__device__ float g_p1[NN];
__device__ float g_p2[NN];
__device__ float g_dinv[4][NN];
__device__ float g_ssum[NN];
__device__ float g_scnt[NN];
__device__ int   g_parent[NN];
__device__ int   g_cl[3][NN];
__device__ int   g_act[3][NN];
__device__ unsigned char g_isact[3][NN];
__device__ int   g_misc[16];
__device__ int   g_esrc[4][EE];
__device__ int   g_edst[4][EE];
__device__ unsigned g_htab[HSZ];
__device__ float g_xw1[NN];
__device__ int   g_coff[4][NN];
__device__ int   g_ccnt[4][NN];
__device__ int   g_csrc[4][EE];
__device__ float g_cnorm[4][EE];
__device__ int   g_cnt[NN];
__device__ int   g_wcur[NN];
__device__ int   g_bsum[256];
// member sort for pooling (realm nodes only)
__device__ int   g_mcnt[NN];
__device__ int   g_moff[NN];
__device__ int   g_mcur[NN];
__device__ int   g_mlist[NN];

// ---------------- kernels ----------------

__global__ void k_copy_edges0(const int* __restrict__ ei) {
    int e = blockIdx.x*blockDim.x + threadIdx.x;
    if (e >= EE) return;
    int s = ei[2*e], d = ei[2*e+1];
    g_esrc[0][e] = s;
    g_edst[0][e] = d;
    atomicAdd(&g_cnt[d], 1);
}

// block scan: outx = within-block exclusive; g_bsum[b] = block total
__global__ void k_scanA(const int* __restrict__ in, int* __restrict__ outx) {
    __shared__ int sh[256];
    int tx = threadIdx.x;
    int v = blockIdx.x*256 + tx;
    int c = (v < NN) ? in[v] : 0;
    sh[tx] = c; __syncthreads();
    int val = c;
    for (int o = 1; o < 256; o <<= 1) {
        int y = (tx >= o) ? sh[tx-o] : 0;
        __syncthreads();
        val += y; sh[tx] = val;
        __syncthreads();
    }
    if (v < NN) outx[v] = val - c;
    if (tx == 255) g_bsum[blockIdx.x] = val;
}

__device__ __forceinline__ int block_prefix_of_bsum() {
    // sum of g_bsum[0..blockIdx.x-1] via block reduction
    __shared__ int red[256];
    int tx = threadIdx.x;
    int contrib = (tx < blockIdx.x) ? g_bsum[tx] : 0;
    red[tx] = contrib; __syncthreads();
    for (int o = 128; o > 0; o >>= 1) {
        if (tx < o) red[tx] += red[tx+o];
        __syncthreads();
    }
    int r = red[0];
    __syncthreads();
    return r;
}

// fused scan2+scan3: finalize CSR offsets + dinv
__global__ void k_scan3f(int t) {
    int boffB = block_prefix_of_bsum();
    int v = blockIdx.x*256 + threadIdx.x;
    if (v >= NN) return;
    int c = g_cnt[v];
    int o = g_coff[t][v] + boffB;
    g_coff[t][v] = o;
    g_wcur[v]    = o;
    g_ccnt[t][v] = c;
    g_dinv[t][v] = rsqrtf(2.0f + (float)c);
}

// fused scan2+mscan3: finalize member offsets + reset parent for next level
__global__ void k_mscan3(void) {
    int boffB = block_prefix_of_bsum();
    int v = blockIdx.x*256 + threadIdx.x;
    if (v >= NN) return;
    int o = g_moff[v] + boffB;
    g_moff[v] = o;
    g_mcur[v] = o;
    g_parent[v] = v;   // re-init for next level's union
}

__global__ void k_fill(int t) {
    int e = blockIdx.x*blockDim.x + threadIdx.x;
    int cnt = (t == 0) ? EE : g_misc[MI_NE + t];
    if (e >= cnt) return;
    int s = g_esrc[t][e], d = g_edst[t][e];
    int pos = atomicAdd(&g_wcur[d], 1);
    g_csrc[t][pos]  = s;
    g_cnorm[t][pos] = g_dinv[t][s] * g_dinv[t][d];
}

// unified 128x128-tile GEMM (kin=128). L<0: dense rows; L>=0: rows from g_act[L].
__global__ void __launch_bounds__(256) k_gemmT(const float* __restrict__ X,
                                               const float* __restrict__ W,
                                               float* __restrict__ out, int L,
                                               int applyScale) {
    __shared__ float Xs[32][132];
    __shared__ float Ws[32][128];
    __shared__ int rows[128];
    __shared__ float rwS[128];
    int count = (L >= 0) ? g_misc[MI_NACT + L] : NN;
    int row0 = blockIdx.x * 128;
    if (row0 >= count) return;
    int tid = threadIdx.x;
    if (tid < 128) {
        int rr = row0 + tid;
        int row = (rr < count) ? ((L >= 0) ? g_act[L][rr] : rr) : -1;
        rows[tid] = row;
        float wv = 1.0f;
        if (applyScale && row >= 0) {
            float c = g_scnt[row];
            wv = (c > 0.0f) ? g_ssum[row] / fmaxf(c, 1.0f) : 1.0f;
        }
        rwS[tid] = wv;
    }
    __syncthreads();
    int cid = tid & 31;
    int rid = tid >> 5;
    float acc[16][4];
#pragma unroll
    for (int r = 0; r < 16; r++) { acc[r][0]=0.f; acc[r][1]=0.f; acc[r][2]=0.f; acc[r][3]=0.f; }
    for (int k0 = 0; k0 < HD; k0 += 32) {
        for (int i = tid; i < 128*8; i += 256) {
            int r = i >> 3, q = i & 7;
            int row = rows[r];
            float4 v = make_float4(0.f,0.f,0.f,0.f);
            if (row >= 0) {
                v = *(const float4*)&X[(size_t)row*HD + k0 + q*4];
                float wv = rwS[r];
                v.x *= wv; v.y *= wv; v.z *= wv; v.w *= wv;
            }
            Xs[q*4+0][r] = v.x; Xs[q*4+1][r] = v.y;
            Xs[q*4+2][r] = v.z; Xs[q*4+3][r] = v.w;
        }
        for (int i = tid; i < 32*128; i += 256) {
            int kk = i >> 7, c = i & 127;
            Ws[kk][c] = W[(size_t)(k0+kk)*HD + c];
        }
        __syncthreads();
#pragma unroll
        for (int kk = 0; kk < 32; kk++) {
            float4 w = *(const float4*)&Ws[kk][cid*4];
#pragma unroll
            for (int r = 0; r < 16; r++) {
                float xr = Xs[kk][rid + 8*r];
                acc[r][0] += xr*w.x; acc[r][1] += xr*w.y;
                acc[r][2] += xr*w.z; acc[r][3] += xr*w.w;
            }
        }
        __syncthreads();
    }
#pragma unroll
    for (int r = 0; r < 16; r++) {
        int row = rows[rid + 8*r];
        if (row >= 0)
            *(float4*)&out[(size_t)row*HD + cid*4] = make_float4(acc[r][0],acc[r][1],acc[r][2],acc[r][3]);
    }
}

__device__ __forceinline__ void conv_row(int t, int v, int lane,
                                         const float* __restrict__ b,
                                         float* __restrict__ out, int dorelu,
                                         const float* __restrict__ Wp,
                                         int useYb, const int* __restrict__ cl,
                                         int initParent) {
    int off = g_coff[t][v], n = g_ccnt[t][v];
    float4 acc = make_float4(0.f,0.f,0.f,0.f);
    for (int i = 0; i < n; i++) {
        int s   = g_csrc[t][off+i];
        float nm = g_cnorm[t][off+i];
        float4 xv = ((const float4*)(g_xw + (size_t)s*HD))[lane];
        if (useYb) {
            float4 yv = ((const float4*)(g_yb + (size_t)cl[s]*HD))[lane];
            xv.x += yv.x; xv.y += yv.y; xv.z += yv.z; xv.w += yv.w;
        }
        acc.x += xv.x*nm; acc.y += xv.y*nm; acc.z += xv.z*nm; acc.w += xv.w*nm;
    }
    float dv = g_dinv[t][v];
    float sc = 2.0f*dv*dv;
    float4 xs = ((const float4*)(g_xw + (size_t)v*HD))[lane];
    if (useYb) {
        float4 yv = ((const float4*)(g_yb + (size_t)cl[v]*HD))[lane];
        xs.x += yv.x; xs.y += yv.y; xs.z += yv.z; xs.w += yv.w;
    }
    float4 bb = ((const float4*)b)[lane];
    float4 o;
    o.x = acc.x + sc*xs.x + bb.x;
    o.y = acc.y + sc*xs.y + bb.y;
    o.z = acc.z + sc*xs.z + bb.z;
    o.w = acc.w + sc*xs.w + bb.w;
    if (dorelu) {
        o.x = fmaxf(o.x,0.f); o.y = fmaxf(o.y,0.f);
        o.z = fmaxf(o.z,0.f); o.w = fmaxf(o.w,0.f);
    }
    ((float4*)(out + (size_t)v*HD))[lane] = o;
    if (Wp) {
        float4 w1 = ((const float4*)Wp)[lane];
        float4 w2 = ((const float4*)(Wp + HD))[lane];
        float a = o.x*w1.x + o.y*w1.y + o.z*w1.z + o.w*w1.w;
        float b2 = o.x*w2.x + o.y*w2.y + o.z*w2.z + o.w*w2.w;
#pragma unroll
        for (int q = 16; q > 0; q >>= 1) {
            a  += __shfl_xor_sync(FULLMASK, a, q);
            b2 += __shfl_xor_sync(FULLMASK, b2, q);
        }
        if (lane == 0) {
            g_p1[v] = a; g_p2[v] = b2;
            if (initParent) g_parent[v] = v;
        }
    }
}

// full-N conv (t0 down path; also inits parent via proj epilogue)
__global__ void k_conv(int t, const float* __restrict__ b, float* __restrict__ out,
                       int dorelu, const float* __restrict__ Wp) {
    int gt = blockIdx.x*blockDim.x + threadIdx.x;
    int v = gt >> 5, lane = gt & 31;
    if (v >= NN) return;
    conv_row(t, v, lane, b, out, dorelu, Wp, 0, (const int*)0, 1);
}

// act-restricted conv: warps loop over g_act[L]
__global__ void k_conv_act(int t, int L, const float* __restrict__ b,
                           float* __restrict__ out, int dorelu,
                           const float* __restrict__ Wp,
                           int useYb, const int* __restrict__ cl) {
    int gw = (blockIdx.x*blockDim.x + threadIdx.x) >> 5;
    int lane = threadIdx.x & 31;
    int na = g_misc[MI_NACT + L];
    for (int j = gw; j < na; j += NBW*8)
        conv_row(t, g_act[L][j], lane, b, out, dorelu, Wp, useYb, cl, 0);
}

__device__ __forceinline__ int uf_find(int x) {
    volatile int* P = g_parent;
    while (true) {
        int p = P[x];
        if (p == x) return x;
        int gp = P[p];
        if (gp == p) return p;
        P[x] = gp;
        x = gp;
    }
}

// sigma(z) > 0.5 <=> z > 0
__global__ void k_score_union(int t, const float* __restrict__ bp) {
    int e = blockIdx.x*blockDim.x + threadIdx.x;
    int cnt = (t == 0) ? EE : g_misc[MI_NE + t];
    if (e >= cnt) return;
    int s = g_esrc[t][e], d = g_edst[t][e];
    float z = g_p1[s] + g_p2[d] + bp[0];
    if (s == d || z <= 0.0f) return;
    if (g_parent[s] == g_parent[d]) return;  // sound: components never split
    int ru = uf_find(s);
    int rv = uf_find(d);
    while (ru != rv) {
        if (ru < rv) { int tt = ru; ru = rv; rv = tt; }
        int old = atomicCAS(&g_parent[ru], ru, rv);
        if (old == ru) break;
        ru = uf_find(old);
        rv = uf_find(rv);
    }
}

// flatten + realm-restricted active append + warp-aggregated member count
// + zero counters for next phase
__global__ void k_flatten(int L) {
    int v = blockIdx.x*blockDim.x + threadIdx.x;
    int lane = threadIdx.x & 31;
    int r = -1;
    bool realm = false;
    if (v < NN) {
        r = uf_find(v);
        g_cl[L][v] = r;
        g_ssum[v] = 0.0f;
        g_scnt[v] = 0.0f;
        g_cnt[v] = 0;
        g_mcnt[v] = 0;
        realm = (L == 0) ? true : (g_isact[L-1][v] != 0);
        unsigned char a = 0;
        if (realm && r == v) {
            int p = atomicAdd(&g_misc[MI_NACT + L], 1);
            g_act[L][p] = v;
            a = 1;
        }
        g_isact[L][v] = a;
    }
    // member count over realm nodes only (warp-aggregated) — needs mcnt zeroed:
    // mcnt zeroing races with the atomicAdd within this same kernel!  Avoid by
    // doing the count in a separate array pass?  No: mcnt was zeroed HERE for the
    // *previous* level already... not for L=0.  Solve by deferring: count into
    // mcnt only AFTER zero via separate kernel is wrong; instead zero mcnt in the
    // PREVIOUS level's mscan3 (and init memset for level 0).
    int c = (v < NN && realm) ? r : -1;
    unsigned m = __match_any_sync(FULLMASK, c);
    int leader = __ffs(m) - 1;
    if (lane == leader && c >= 0) atomicAdd(&g_mcnt[c], __popc(m));
}

// fused: seg (score sums) + compacting relabel/dedup + next degree count
__global__ void k_seg_relabel(int tin, int L, const float* __restrict__ bp) {
    int e = blockIdx.x*blockDim.x + threadIdx.x;
    int lane = threadIdx.x & 31;
    int cnt = (tin == 0) ? EE : g_misc[MI_NE + tin];
    float sval = 0.0f; int c = -1;
    if (e < cnt) {
        int s = g_esrc[tin][e], d = g_edst[tin][e];
        int a = g_cl[L][s];
        int b = g_cl[L][d];
        float z = g_p1[s] + g_p2[d] + bp[0];
        if (s != d && z > 0.0f) {
            sval = 1.0f / (1.0f + expf(-z));
            c = a;
        }
        if (a != b) {
            unsigned key = (unsigned)a * (unsigned)NN + (unsigned)b;
            unsigned h = (unsigned)(((unsigned long long)key * 2654435761u) >> 11) & (HSZ-1);
            while (true) {
                unsigned old = atomicCAS(&g_htab[h], 0xFFFFFFFFu, key);
                if (old == 0xFFFFFFFFu) {
                    int pos = atomicAdd(&g_misc[MI_NE + tin + 1], 1);
                    g_esrc[tin+1][pos] = a;
                    g_edst[tin+1][pos] = b;
                    atomicAdd(&g_cnt[b], 1);
                    break;
                }
                if (old == key) break;
                h = (h + 1) & (HSZ-1);
            }
        }
    }
    unsigned m = __match_any_sync(FULLMASK, c);
    int leader = __ffs(m) - 1;
    float tot = 0.0f;
#pragma unroll
    for (int j = 0; j < 32; j++) {
        float os = __shfl_sync(FULLMASK, sval, j);
        int   oc = __shfl_sync(FULLMASK, c, j);
        if (lane == leader && c >= 0 && oc == c) tot += os;
    }
    if (lane == leader && c >= 0) {
        atomicAdd(&g_ssum[c], tot);
        atomicAdd(&g_scnt[c], (float)__popc(m));
    }
}

// mfill: realm nodes appended into mlist (sorted by cluster)
__global__ void k_mfill(int L) {
    int v = blockIdx.x*blockDim.x + threadIdx.x;
    int lane = threadIdx.x & 31;
    int c = -1;
    if (v < NN) {
        bool realm = (L == 0) ? true : (g_isact[L-1][v] != 0);
        if (realm) c = g_cl[L][v];
    }
    unsigned m = __match_any_sync(FULLMASK, c);
    int leader = __ffs(m) - 1;
    int rank = __popc(m & ((1u << lane) - 1u));
    int base = 0;
    if (lane == leader && c >= 0) base = atomicAdd(&g_mcur[c], __popc(m));
    base = __shfl_sync(FULLMASK, base, leader);
    if (c >= 0) g_mlist[base + rank] = v;
}

// block per 128-member chunk of mlist[0..nmem); uniform-cluster fast path
__global__ void __launch_bounds__(256) k_poolacc(int L, const float* __restrict__ x,
                                                 float* __restrict__ xn) {
    __shared__ int tot_s;
    if (threadIdx.x == 0)
        tot_s = (L == 0) ? NN : g_misc[MI_NACT + L - 1];
    __syncthreads();
    int total = tot_s;
    int chunk0 = blockIdx.x * 128;
    if (chunk0 >= total) return;
    int n = total - chunk0; if (n > 128) n = 128;
    int tid = threadIdx.x;
    int f = tid & 127, half = tid >> 7;
    __shared__ float acc[2][128];
    __shared__ int c0s, unif;
    if (tid == 0) {
        int ca = g_cl[L][g_mlist[chunk0]];
        int cb = g_cl[L][g_mlist[chunk0 + n - 1]];
        c0s = ca; unif = (ca == cb);
    }
    __syncthreads();
    if (unif) {
        float a = 0.0f;
        for (int j = half; j < n; j += 2)
            a += x[(size_t)g_mlist[chunk0 + j]*HD + f];
        acc[half][f] = a;
        __syncthreads();
        if (half == 0)
            atomicAdd(&xn[(size_t)c0s*HD + f], acc[0][f] + acc[1][f]);
    } else {
        int lane4 = tid & 31;
        for (int j = tid >> 5; j < n; j += 8) {
            int mv = g_mlist[chunk0 + j];
            int c = g_cl[L][mv];
            float4 val = ((const float4*)(x + (size_t)mv*HD))[lane4];
            atomicAdd(((float4*)(xn + (size_t)c*HD)) + lane4, val);
        }
    }
}

__global__ void k_yb2(const float* __restrict__ xup, const float* __restrict__ Wu2c) {
    int gw = (blockIdx.x*blockDim.x + threadIdx.x) >> 5;
    int lane = threadIdx.x & 31;
    int na = g_misc[MI_NACT + 0];
    for (int j = gw; j < na; j += NBW*8) {
        int row = g_act[0][j];
        float4 xv = ((const float4*)(xup + (size_t)row*HD))[lane];
        float4 wv = ((const float4*)Wu2c)[lane];
        float a = xv.x*wv.x + xv.y*wv.y + xv.z*wv.z + xv.w*wv.w;
#pragma unroll
        for (int o = 16; o > 0; o >>= 1) a += __shfl_xor_sync(FULLMASK, a, o);
        if (lane == 0) g_p1[row] = a;
    }
}

__global__ void k_xw1(const float* __restrict__ m0, const float* __restrict__ xin,
                      const float* __restrict__ Wu2) {
    int gt = blockIdx.x*blockDim.x + threadIdx.x;
    int v = gt >> 5, lane = gt & 31;
    if (v >= NN) return;
    float4 x1 = ((const float4*)(m0  + (size_t)v*HD))[lane];
    float4 x2 = ((const float4*)(xin + (size_t)v*HD))[lane];
    float4 w1 = ((const float4*)Wu2)[lane];
    float4 w2 = ((const float4*)(Wu2 + HD))[lane];
    float a = x1.x*w1.x + x1.y*w1.y + x1.z*w1.z + x1.w*w1.w
            + x2.x*w2.x + x2.y*w2.y + x2.z*w2.z + x2.w*w2.w;
#pragma unroll
    for (int o = 16; o > 0; o >>= 1) a += __shfl_xor_sync(FULLMASK, a, o);
    if (lane == 0) g_xw1[v] = a + g_p1[g_cl[0][v]];
}

__global__ void k_conv1(const float* __restrict__ bu, float* __restrict__ out) {
    int gt = blockIdx.x*blockDim.x + threadIdx.x;
    int v = gt >> 5, lane = gt & 31;
    if (v >= NN) return;
    int off = g_coff[0][v], n = g_ccnt[0][v];
    float acc = 0.0f;
    for (int i = lane; i < n; i += 32)
        acc += g_xw1[g_csrc[0][off+i]] * g_cnorm[0][off+i];
#pragma unroll
    for (int o = 16; o > 0; o >>= 1) acc += __shfl_xor_sync(FULLMASK, acc, o);
    if (lane == 0) {
        float dv = g_dinv[0][v];
        float z = acc + 2.0f*dv*dv*g_xw1[v] + bu[0];
        out[v] = 1.0f / (1.0f + expf(-z));
    }
}

// ---------------- host orchestration ----------------

extern "C" void kernel_launch(void* const* d_in, const int* in_sizes, int n_in,
                              void* d_out, int out_size) {
    (void)in_sizes; (void)n_in; (void)out_size;
    const float* x_in = (const float*)d_in[0];
    const int*   ei   = (const int*)d_in[1];
    const float* Wd[4] = {(const float*)d_in[3],(const float*)d_in[5],(const float*)d_in[7],(const float*)d_in[9]};
    const float* bd[4] = {(const float*)d_in[4],(const float*)d_in[6],(const float*)d_in[8],(const float*)d_in[10]};
    const float* Wp[3] = {(const float*)d_in[11],(const float*)d_in[13],(const float*)d_in[15]};
    const float* bp[3] = {(const float*)d_in[12],(const float*)d_in[14],(const float*)d_in[16]};
    const float* Wu[3] = {(const float*)d_in[17],(const float*)d_in[19],(const float*)d_in[21]};
    const float* bu[3] = {(const float*)d_in[18],(const float*)d_in[20],(const float*)d_in[22]};
    float* out = (float*)d_out;

    void* pv;
    float *p_xa, *p_xb, *p_cv, *p_m0, *p_m1, *p_m2, *p_xw, *p_yb;
    int *p_cnt, *p_misc, *p_mcnt, *p_moff, *p_cl; unsigned *p_htab;
    cudaGetSymbolAddress(&pv, g_xa);   p_xa   = (float*)pv;
    cudaGetSymbolAddress(&pv, g_xb);   p_xb   = (float*)pv;
    cudaGetSymbolAddress(&pv, g_cv);   p_cv   = (float*)pv;
    cudaGetSymbolAddress(&pv, g_m0);   p_m0   = (float*)pv;
    cudaGetSymbolAddress(&pv, g_m1);   p_m1   = (float*)pv;
    cudaGetSymbolAddress(&pv, g_m2);   p_m2   = (float*)pv;
    cudaGetSymbolAddress(&pv, g_xw);   p_xw   = (float*)pv;
    cudaGetSymbolAddress(&pv, g_yb);   p_yb   = (float*)pv;
    cudaGetSymbolAddress(&pv, g_cnt);  p_cnt  = (int*)pv;
    cudaGetSymbolAddress(&pv, g_misc); p_misc = (int*)pv;
    cudaGetSymbolAddress(&pv, g_mcnt); p_mcnt = (int*)pv;
    cudaGetSymbolAddress(&pv, g_moff); p_moff = (int*)pv;
    cudaGetSymbolAddress(&pv, g_cl);   p_cl   = (int*)pv;
    cudaGetSymbolAddress(&pv, g_htab); p_htab = (unsigned*)pv;
    int* coffp;
    cudaGetSymbolAddress(&pv, g_coff); coffp = (int*)pv;

    const int gN  = (NN + NT - 1) / NT;
    const int gE  = (EE + NT - 1) / NT;
    const int gNw = (NN*32 + NT - 1) / NT;
    const int gG  = (NN + 127) / 128;

    cudaMemsetAsync(p_cnt, 0, NN*sizeof(int));
    cudaMemsetAsync(p_mcnt, 0, NN*sizeof(int));   // level-0 mcnt (later levels: zeroed in flatten)
    cudaMemsetAsync(p_misc, 0, 16*sizeof(int));
    k_copy_edges0<<<gE, NT>>>(ei);

    const float* Xin[3]  = { x_in, p_xa, p_xb };
    float*       memb[3] = { p_m0, p_m1, p_m2 };
    float*       xout[3] = { p_xa, p_xb, p_xa };

    for (int i = 0; i < 3; i++) {
        int t = i;
        k_scanA<<<NB, 256>>>(p_cnt, coffp + t*NN);
        if (i == 0) k_gemmT<<<gG, 256>>>(x_in, Wd[0], p_xw, -1, 0);
        else        k_gemmT<<<gG, 256>>>(Xin[i], Wd[i], p_xw, i-1, 1);
        k_scan3f<<<NB, 256>>>(t);
        k_fill<<<gE, NT>>>(t);
        if (i == 0) k_conv<<<gNw, NT>>>(0, bd[0], memb[0], 1, Wp[0]);
        else        k_conv_act<<<NBW, NT>>>(t, i-1, bd[i], memb[i], 1, Wp[i], 0, (const int*)0);
        k_score_union<<<gE, NT>>>(t, bp[i]);
        k_flatten<<<gN, NT>>>(i);
        cudaMemsetAsync(xout[i], 0, (size_t)NN*HD*sizeof(float));
        cudaMemsetAsync(p_htab, 0xFF, HSZ*sizeof(unsigned));
        k_seg_relabel<<<gE, NT>>>(t, i, bp[i]);
        k_scanA<<<NB, 256>>>(p_mcnt, p_moff);
        k_mscan3<<<NB, 256>>>();        // also resets parent for next level
        k_mfill<<<gN, NT>>>(i);
        k_poolacc<<<gG, 256>>>(i, memb[i], xout[i]);
    }

    // ---- bottom conv (topology 3, rows act[2]) ----
    k_scanA<<<NB, 256>>>(p_cnt, coffp + 3*NN);
    k_gemmT<<<gG, 256>>>(p_xa, Wd[3], p_xw, 2, 1);
    k_scan3f<<<NB, 256>>>(3);
    k_fill<<<gE, NT>>>(3);
    k_conv_act<<<NBW, NT>>>(3, 2, bd[3], p_cv, 0, (const float*)0, 0, (const int*)0);

    // ---- UP 0 : rows act[1], topology 2 ----
    k_gemmT<<<gG, 256>>>(p_m2, Wu[0], p_xw, 1, 0);             // mem @ Wu_top (act[1])
    k_gemmT<<<gG, 256>>>(p_cv, Wu[0] + 128*HD, p_yb, 2, 0);    // xup @ Wu_bot (act[2])
    k_conv_act<<<NBW, NT>>>(2, 1, bu[0], p_xa, 1, (const float*)0, 1, p_cl + 2*NN);

    // ---- UP 1 : rows act[0], topology 1 ----
    k_gemmT<<<gG, 256>>>(p_m1, Wu[1], p_xw, 0, 0);             // mem @ Wu_top (act[0])
    k_gemmT<<<gG, 256>>>(p_xa, Wu[1] + 128*HD, p_yb, 1, 0);    // xup @ Wu_bot (act[1])
    k_conv_act<<<NBW, NT>>>(1, 0, bu[1], p_xb, 1, (const float*)0, 1, p_cl + 1*NN);

    // ---- UP 2 : full N, topology 0, output dim 1 ----
    k_yb2<<<NBW, NT>>>(p_xb, Wu[2] + 256);
    k_xw1<<<gNw, NT>>>(p_m0, x_in, Wu[2]);
    k_conv1<<<gNw, NT>>>(bu[2], out);
}

// round 10
// speedup vs baseline: 1.8324x; 1.0013x over previous
#include <cuda_runtime.h>
#include <math.h>

#define NN 50000
#define EE 800000
#define HD 128
#define HSZ (1u<<20)
#define NT 256
#define FULLMASK 0xffffffffu
#define NB 196   // (NN+255)/256
#define NBW 512

#define MI_NACT 0
#define MI_NE   4
// ---------------- static device scratch ----------------
__device__ float g_xw[NN*HD];
__device__ float g_cv[NN*HD];
__device__ float g_xa[NN*HD];
__device__ float g_xb[NN*HD];
__device__ float g_m0[NN*HD];
__device__ float g_m1[NN*HD];
__device__ float g_m2[NN*HD];
__device__ float g_yb[NN*HD];
__device__ float g_p1[NN];
__device__ float g_p2[NN];
__device__ float g_dinv[4][NN];
__device__ float g_ssum[NN];
__device__ float g_scnt[NN];
__device__ int   g_parent[NN];
__device__ int   g_cl[3][NN];
__device__ int   g_act[3][NN];
__device__ unsigned char g_isact[3][NN];
__device__ int   g_misc[16];
__device__ int   g_esrc[4][EE];   // [0] unused (t0 reads ei directly)
__device__ int   g_edst[4][EE];
__device__ unsigned g_htab[HSZ];
__device__ float g_xw1[NN];
__device__ int   g_coff[4][NN];
__device__ int   g_ccnt[4][NN];
__device__ int   g_csrc[4][EE];
__device__ float g_cnorm[4][EE];
__device__ int   g_cnt[NN];
__device__ int   g_wcur[NN];
__device__ int   g_bsum[256];
__device__ int   g_mcnt[NN];
__device__ int   g_moff[NN];
__device__ int   g_mcur[NN];
__device__ int   g_mlist[NN];

// ---------------- kernels ----------------

// one-shot init: counters
__global__ void k_init() {
    int v = blockIdx.x*blockDim.x + threadIdx.x;
    if (v < NN) { g_cnt[v] = 0; g_mcnt[v] = 0; }
    if (v < 16) g_misc[v] = 0;
}

__global__ void k_cnt0(const int2* __restrict__ e0) {
    int e = blockIdx.x*blockDim.x + threadIdx.x;
    if (e >= EE) return;
    atomicAdd(&g_cnt[e0[e].y], 1);
}

// block scan: outx = within-block exclusive; g_bsum[b] = block total
__global__ void k_scanA(const int* __restrict__ in, int* __restrict__ outx) {
    __shared__ int sh[256];
    int tx = threadIdx.x;
    int v = blockIdx.x*256 + tx;
    int c = (v < NN) ? in[v] : 0;
    sh[tx] = c; __syncthreads();
    int val = c;
    for (int o = 1; o < 256; o <<= 1) {
        int y = (tx >= o) ? sh[tx-o] : 0;
        __syncthreads();
        val += y; sh[tx] = val;
        __syncthreads();
    }
    if (v < NN) outx[v] = val - c;
    if (tx == 255) g_bsum[blockIdx.x] = val;
}

__device__ __forceinline__ int block_prefix_of_bsum() {
    __shared__ int red[256];
    int tx = threadIdx.x;
    int contrib = (tx < blockIdx.x) ? g_bsum[tx] : 0;
    red[tx] = contrib; __syncthreads();
    for (int o = 128; o > 0; o >>= 1) {
        if (tx < o) red[tx] += red[tx+o];
        __syncthreads();
    }
    int r = red[0];
    __syncthreads();
    return r;
}

__global__ void k_scan3f(int t) {
    int boffB = block_prefix_of_bsum();
    int v = blockIdx.x*256 + threadIdx.x;
    if (v >= NN) return;
    int c = g_cnt[v];
    int o = g_coff[t][v] + boffB;
    g_coff[t][v] = o;
    g_wcur[v]    = o;
    g_ccnt[t][v] = c;
    g_dinv[t][v] = rsqrtf(2.0f + (float)c);
}

__global__ void k_mscan3(void) {
    int boffB = block_prefix_of_bsum();
    int v = blockIdx.x*256 + threadIdx.x;
    if (v >= NN) return;
    int o = g_moff[v] + boffB;
    g_moff[v] = o;
    g_mcur[v] = o;
    g_parent[v] = v;
}

__global__ void k_fill(int t, const int2* __restrict__ e0) {
    int e = blockIdx.x*blockDim.x + threadIdx.x;
    int cnt = (t == 0) ? EE : g_misc[MI_NE + t];
    if (e >= cnt) return;
    int s, d;
    if (t == 0) { int2 sd = e0[e]; s = sd.x; d = sd.y; }
    else        { s = g_esrc[t][e]; d = g_edst[t][e]; }
    int pos = atomicAdd(&g_wcur[d], 1);
    g_csrc[t][pos]  = s;
    g_cnorm[t][pos] = g_dinv[t][s] * g_dinv[t][d];
}

// unified 128x128-tile GEMM (kin=128). L<0: dense rows; L>=0: rows from g_act[L].
__global__ void __launch_bounds__(256) k_gemmT(const float* __restrict__ X,
                                               const float* __restrict__ W,
                                               float* __restrict__ out, int L,
                                               int applyScale) {
    __shared__ float Xs[32][132];
    __shared__ float Ws[32][128];
    __shared__ int rows[128];
    __shared__ float rwS[128];
    int count = (L >= 0) ? g_misc[MI_NACT + L] : NN;
    int row0 = blockIdx.x * 128;
    if (row0 >= count) return;
    int tid = threadIdx.x;
    if (tid < 128) {
        int rr = row0 + tid;
        int row = (rr < count) ? ((L >= 0) ? g_act[L][rr] : rr) : -1;
        rows[tid] = row;
        float wv = 1.0f;
        if (applyScale && row >= 0) {
            float c = g_scnt[row];
            wv = (c > 0.0f) ? g_ssum[row] / fmaxf(c, 1.0f) : 1.0f;
        }
        rwS[tid] = wv;
    }
    __syncthreads();
    int cid = tid & 31;
    int rid = tid >> 5;
    float acc[16][4];
#pragma unroll
    for (int r = 0; r < 16; r++) { acc[r][0]=0.f; acc[r][1]=0.f; acc[r][2]=0.f; acc[r][3]=0.f; }
    for (int k0 = 0; k0 < HD; k0 += 32) {
        for (int i = tid; i < 128*8; i += 256) {
            int r = i >> 3, q = i & 7;
            int row = rows[r];
            float4 v = make_float4(0.f,0.f,0.f,0.f);
            if (row >= 0) {
                v = *(const float4*)&X[(size_t)row*HD + k0 + q*4];
                float wv = rwS[r];
                v.x *= wv; v.y *= wv; v.z *= wv; v.w *= wv;
            }
            Xs[q*4+0][r] = v.x; Xs[q*4+1][r] = v.y;
            Xs[q*4+2][r] = v.z; Xs[q*4+3][r] = v.w;
        }
        for (int i = tid; i < 32*128; i += 256) {
            int kk = i >> 7, c = i & 127;
            Ws[kk][c] = W[(size_t)(k0+kk)*HD + c];
        }
        __syncthreads();
#pragma unroll
        for (int kk = 0; kk < 32; kk++) {
            float4 w = *(const float4*)&Ws[kk][cid*4];
#pragma unroll
            for (int r = 0; r < 16; r++) {
                float xr = Xs[kk][rid + 8*r];
                acc[r][0] += xr*w.x; acc[r][1] += xr*w.y;
                acc[r][2] += xr*w.z; acc[r][3] += xr*w.w;
            }
        }
        __syncthreads();
    }
#pragma unroll
    for (int r = 0; r < 16; r++) {
        int row = rows[rid + 8*r];
        if (row >= 0)
            *(float4*)&out[(size_t)row*HD + cid*4] = make_float4(acc[r][0],acc[r][1],acc[r][2],acc[r][3]);
    }
}

__device__ __forceinline__ void conv_row(int t, int v, int lane,
                                         const float* __restrict__ b,
                                         float* __restrict__ out, int dorelu,
                                         const float* __restrict__ Wp,
                                         int useYb, const int* __restrict__ cl,
                                         int initParent) {
    int off = g_coff[t][v], n = g_ccnt[t][v];
    float4 acc = make_float4(0.f,0.f,0.f,0.f);
    for (int i = 0; i < n; i++) {
        int s   = g_csrc[t][off+i];
        float nm = g_cnorm[t][off+i];
        float4 xv = ((const float4*)(g_xw + (size_t)s*HD))[lane];
        if (useYb) {
            float4 yv = ((const float4*)(g_yb + (size_t)cl[s]*HD))[lane];
            xv.x += yv.x; xv.y += yv.y; xv.z += yv.z; xv.w += yv.w;
        }
        acc.x += xv.x*nm; acc.y += xv.y*nm; acc.z += xv.z*nm; acc.w += xv.w*nm;
    }
    float dv = g_dinv[t][v];
    float sc = 2.0f*dv*dv;
    float4 xs = ((const float4*)(g_xw + (size_t)v*HD))[lane];
    if (useYb) {
        float4 yv = ((const float4*)(g_yb + (size_t)cl[v]*HD))[lane];
        xs.x += yv.x; xs.y += yv.y; xs.z += yv.z; xs.w += yv.w;
    }
    float4 bb = ((const float4*)b)[lane];
    float4 o;
    o.x = acc.x + sc*xs.x + bb.x;
    o.y = acc.y + sc*xs.y + bb.y;
    o.z = acc.z + sc*xs.z + bb.z;
    o.w = acc.w + sc*xs.w + bb.w;
    if (dorelu) {
        o.x = fmaxf(o.x,0.f); o.y = fmaxf(o.y,0.f);
        o.z = fmaxf(o.z,0.f); o.w = fmaxf(o.w,0.f);
    }
    ((float4*)(out + (size_t)v*HD))[lane] = o;
    if (Wp) {
        float4 w1 = ((const float4*)Wp)[lane];
        float4 w2 = ((const float4*)(Wp + HD))[lane];
        float a = o.x*w1.x + o.y*w1.y + o.z*w1.z + o.w*w1.w;
        float b2 = o.x*w2.x + o.y*w2.y + o.z*w2.z + o.w*w2.w;
#pragma unroll
        for (int q = 16; q > 0; q >>= 1) {
            a  += __shfl_xor_sync(FULLMASK, a, q);
            b2 += __shfl_xor_sync(FULLMASK, b2, q);
        }
        if (lane == 0) {
            g_p1[v] = a; g_p2[v] = b2;
            if (initParent) g_parent[v] = v;
        }
    }
}

__global__ void k_conv(int t, const float* __restrict__ b, float* __restrict__ out,
                       int dorelu, const float* __restrict__ Wp) {
    int gt = blockIdx.x*blockDim.x + threadIdx.x;
    int v = gt >> 5, lane = gt & 31;
    if (v >= NN) return;
    conv_row(t, v, lane, b, out, dorelu, Wp, 0, (const int*)0, 1);
}

__global__ void k_conv_act(int t, int L, const float* __restrict__ b,
                           float* __restrict__ out, int dorelu,
                           const float* __restrict__ Wp,
                           int useYb, const int* __restrict__ cl) {
    int gw = (blockIdx.x*blockDim.x + threadIdx.x) >> 5;
    int lane = threadIdx.x & 31;
    int na = g_misc[MI_NACT + L];
    for (int j = gw; j < na; j += NBW*8)
        conv_row(t, g_act[L][j], lane, b, out, dorelu, Wp, useYb, cl, 0);
}

__device__ __forceinline__ int uf_find(int x) {
    volatile int* P = g_parent;
    while (true) {
        int p = P[x];
        if (p == x) return x;
        int gp = P[p];
        if (gp == p) return p;
        P[x] = gp;
        x = gp;
    }
}

__global__ void k_score_union(int t, const float* __restrict__ bp,
                              const int2* __restrict__ e0) {
    int e = blockIdx.x*blockDim.x + threadIdx.x;
    int cnt = (t == 0) ? EE : g_misc[MI_NE + t];
    if (e >= cnt) return;
    int s, d;
    if (t == 0) { int2 sd = e0[e]; s = sd.x; d = sd.y; }
    else        { s = g_esrc[t][e]; d = g_edst[t][e]; }
    float z = g_p1[s] + g_p2[d] + bp[0];
    if (s == d || z <= 0.0f) return;
    if (g_parent[s] == g_parent[d]) return;
    int ru = uf_find(s);
    int rv = uf_find(d);
    while (ru != rv) {
        if (ru < rv) { int tt = ru; ru = rv; rv = tt; }
        int old = atomicCAS(&g_parent[ru], ru, rv);
        if (old == ru) break;
        ru = uf_find(old);
        rv = uf_find(rv);
    }
}

__global__ void k_flatten(int L) {
    int v = blockIdx.x*blockDim.x + threadIdx.x;
    int lane = threadIdx.x & 31;
    int r = -1;
    bool realm = false;
    if (v < NN) {
        r = uf_find(v);
        g_cl[L][v] = r;
        g_ssum[v] = 0.0f;
        g_scnt[v] = 0.0f;
        g_cnt[v] = 0;
        g_mcnt[v] = 0;
        realm = (L == 0) ? true : (g_isact[L-1][v] != 0);
        unsigned char a = 0;
        if (realm && r == v) {
            int p = atomicAdd(&g_misc[MI_NACT + L], 1);
            g_act[L][p] = v;
            a = 1;
        }
        g_isact[L][v] = a;
    }
    int c = (v < NN && realm) ? r : -1;
    unsigned m = __match_any_sync(FULLMASK, c);
    int leader = __ffs(m) - 1;
    if (lane == leader && c >= 0) atomicAdd(&g_mcnt[c], __popc(m));
}

__global__ void k_seg_relabel(int tin, int L, const float* __restrict__ bp,
                              const int2* __restrict__ e0) {
    int e = blockIdx.x*blockDim.x + threadIdx.x;
    int lane = threadIdx.x & 31;
    int cnt = (tin == 0) ? EE : g_misc[MI_NE + tin];
    float sval = 0.0f; int c = -1;
    if (e < cnt) {
        int s, d;
        if (tin == 0) { int2 sd = e0[e]; s = sd.x; d = sd.y; }
        else          { s = g_esrc[tin][e]; d = g_edst[tin][e]; }
        int a = g_cl[L][s];
        int b = g_cl[L][d];
        float z = g_p1[s] + g_p2[d] + bp[0];
        if (s != d && z > 0.0f) {
            sval = 1.0f / (1.0f + expf(-z));
            c = a;
        }
        if (a != b) {
            unsigned key = (unsigned)a * (unsigned)NN + (unsigned)b;
            unsigned h = (unsigned)(((unsigned long long)key * 2654435761u) >> 11) & (HSZ-1);
            while (true) {
                unsigned old = atomicCAS(&g_htab[h], 0xFFFFFFFFu, key);
                if (old == 0xFFFFFFFFu) {
                    int pos = atomicAdd(&g_misc[MI_NE + tin + 1], 1);
                    g_esrc[tin+1][pos] = a;
                    g_edst[tin+1][pos] = b;
                    atomicAdd(&g_cnt[b], 1);
                    break;
                }
                if (old == key) break;
                h = (h + 1) & (HSZ-1);
            }
        }
    }
    unsigned m = __match_any_sync(FULLMASK, c);
    int leader = __ffs(m) - 1;
    float tot = 0.0f;
#pragma unroll
    for (int j = 0; j < 32; j++) {
        float os = __shfl_sync(FULLMASK, sval, j);
        int   oc = __shfl_sync(FULLMASK, c, j);
        if (lane == leader && c >= 0 && oc == c) tot += os;
    }
    if (lane == leader && c >= 0) {
        atomicAdd(&g_ssum[c], tot);
        atomicAdd(&g_scnt[c], (float)__popc(m));
    }
}

// mfill: realm nodes into mlist (grouped by cluster) + zero xout act-rows
__global__ void k_mfill(int L, float* __restrict__ xout) {
    int v = blockIdx.x*blockDim.x + threadIdx.x;
    int lane = threadIdx.x & 31;
    int c = -1;
    bool isrep = false;
    if (v < NN) {
        bool realm = (L == 0) ? true : (g_isact[L-1][v] != 0);
        if (realm) c = g_cl[L][v];
        isrep = (g_isact[L][v] != 0);
    }
    unsigned m = __match_any_sync(FULLMASK, c);
    int leader = __ffs(m) - 1;
    int rank = __popc(m & ((1u << lane) - 1u));
    int base = 0;
    if (lane == leader && c >= 0) base = atomicAdd(&g_mcur[c], __popc(m));
    base = __shfl_sync(FULLMASK, base, leader);
    if (c >= 0) g_mlist[base + rank] = v;
    if (isrep) {
        float4 z = make_float4(0.f,0.f,0.f,0.f);
        float4* row = (float4*)(xout + (size_t)v*HD);
#pragma unroll
        for (int q = 0; q < 32; q++) row[q] = z;
    }
}

__global__ void __launch_bounds__(256) k_poolacc(int L, const float* __restrict__ x,
                                                 float* __restrict__ xn) {
    __shared__ int tot_s;
    if (threadIdx.x == 0)
        tot_s = (L == 0) ? NN : g_misc[MI_NACT + L - 1];
    __syncthreads();
    int total = tot_s;
    int chunk0 = blockIdx.x * 128;
    if (chunk0 >= total) return;
    int n = total - chunk0; if (n > 128) n = 128;
    int tid = threadIdx.x;
    int f = tid & 127, half = tid >> 7;
    __shared__ float acc[2][128];
    __shared__ int c0s, unif;
    if (tid == 0) {
        int ca = g_cl[L][g_mlist[chunk0]];
        int cb = g_cl[L][g_mlist[chunk0 + n - 1]];
        c0s = ca; unif = (ca == cb);
    }
    __syncthreads();
    if (unif) {
        float a = 0.0f;
        for (int j = half; j < n; j += 2)
            a += x[(size_t)g_mlist[chunk0 + j]*HD + f];
        acc[half][f] = a;
        __syncthreads();
        if (half == 0)
            atomicAdd(&xn[(size_t)c0s*HD + f], acc[0][f] + acc[1][f]);
    } else {
        int lane4 = tid & 31;
        for (int j = tid >> 5; j < n; j += 8) {
            int mv = g_mlist[chunk0 + j];
            int c = g_cl[L][mv];
            float4 val = ((const float4*)(x + (size_t)mv*HD))[lane4];
            atomicAdd(((float4*)(xn + (size_t)c*HD)) + lane4, val);
        }
    }
}

__global__ void k_yb2(const float* __restrict__ xup, const float* __restrict__ Wu2c) {
    int gw = (blockIdx.x*blockDim.x + threadIdx.x) >> 5;
    int lane = threadIdx.x & 31;
    int na = g_misc[MI_NACT + 0];
    for (int j = gw; j < na; j += NBW*8) {
        int row = g_act[0][j];
        float4 xv = ((const float4*)(xup + (size_t)row*HD))[lane];
        float4 wv = ((const float4*)Wu2c)[lane];
        float a = xv.x*wv.x + xv.y*wv.y + xv.z*wv.z + xv.w*wv.w;
#pragma unroll
        for (int o = 16; o > 0; o >>= 1) a += __shfl_xor_sync(FULLMASK, a, o);
        if (lane == 0) g_p1[row] = a;
    }
}

__global__ void k_xw1(const float* __restrict__ m0, const float* __restrict__ xin,
                      const float* __restrict__ Wu2) {
    int gt = blockIdx.x*blockDim.x + threadIdx.x;
    int v = gt >> 5, lane = gt & 31;
    if (v >= NN) return;
    float4 x1 = ((const float4*)(m0  + (size_t)v*HD))[lane];
    float4 x2 = ((const float4*)(xin + (size_t)v*HD))[lane];
    float4 w1 = ((const float4*)Wu2)[lane];
    float4 w2 = ((const float4*)(Wu2 + HD))[lane];
    float a = x1.x*w1.x + x1.y*w1.y + x1.z*w1.z + x1.w*w1.w
            + x2.x*w2.x + x2.y*w2.y + x2.z*w2.z + x2.w*w2.w;
#pragma unroll
    for (int o = 16; o > 0; o >>= 1) a += __shfl_xor_sync(FULLMASK, a, o);
    if (lane == 0) g_xw1[v] = a + g_p1[g_cl[0][v]];
}

__global__ void k_conv1(const float* __restrict__ bu, float* __restrict__ out) {
    int gt = blockIdx.x*blockDim.x + threadIdx.x;
    int v = gt >> 5, lane = gt & 31;
    if (v >= NN) return;
    int off = g_coff[0][v], n = g_ccnt[0][v];
    float acc = 0.0f;
    for (int i = lane; i < n; i += 32)
        acc += g_xw1[g_csrc[0][off+i]] * g_cnorm[0][off+i];
#pragma unroll
    for (int o = 16; o > 0; o >>= 1) acc += __shfl_xor_sync(FULLMASK, acc, o);
    if (lane == 0) {
        float dv = g_dinv[0][v];
        float z = acc + 2.0f*dv*dv*g_xw1[v] + bu[0];
        out[v] = 1.0f / (1.0f + expf(-z));
    }
}

// ---------------- host orchestration ----------------

extern "C" void kernel_launch(void* const* d_in, const int* in_sizes, int n_in,
                              void* d_out, int out_size) {
    (void)in_sizes; (void)n_in; (void)out_size;
    const float* x_in = (const float*)d_in[0];
    const int2*  e0   = (const int2*)d_in[1];
    const float* Wd[4] = {(const float*)d_in[3],(const float*)d_in[5],(const float*)d_in[7],(const float*)d_in[9]};
    const float* bd[4] = {(const float*)d_in[4],(const float*)d_in[6],(const float*)d_in[8],(const float*)d_in[10]};
    const float* Wp[3] = {(const float*)d_in[11],(const float*)d_in[13],(const float*)d_in[15]};
    const float* bp[3] = {(const float*)d_in[12],(const float*)d_in[14],(const float*)d_in[16]};
    const float* Wu[3] = {(const float*)d_in[17],(const float*)d_in[19],(const float*)d_in[21]};
    const float* bu[3] = {(const float*)d_in[18],(const float*)d_in[20],(const float*)d_in[22]};
    float* out = (float*)d_out;

    void* pv;
    float *p_xa, *p_xb, *p_cv, *p_m0, *p_m1, *p_m2, *p_xw;
    int *p_cnt, *p_mcnt, *p_moff, *p_cl; unsigned *p_htab;
    cudaGetSymbolAddress(&pv, g_xa);   p_xa   = (float*)pv;
    cudaGetSymbolAddress(&pv, g_xb);   p_xb   = (float*)pv;
    cudaGetSymbolAddress(&pv, g_cv);   p_cv   = (float*)pv;
    cudaGetSymbolAddress(&pv, g_m0);   p_m0   = (float*)pv;
    cudaGetSymbolAddress(&pv, g_m1);   p_m1   = (float*)pv;
    cudaGetSymbolAddress(&pv, g_m2);   p_m2   = (float*)pv;
    cudaGetSymbolAddress(&pv, g_xw);   p_xw   = (float*)pv;
    cudaGetSymbolAddress(&pv, g_cnt);  p_cnt  = (int*)pv;
    cudaGetSymbolAddress(&pv, g_mcnt); p_mcnt = (int*)pv;
    cudaGetSymbolAddress(&pv, g_moff); p_moff = (int*)pv;
    cudaGetSymbolAddress(&pv, g_cl);   p_cl   = (int*)pv;
    cudaGetSymbolAddress(&pv, g_htab); p_htab = (unsigned*)pv;
    float* p_yb;
    cudaGetSymbolAddress(&pv, g_yb);   p_yb   = (float*)pv;
    int* coffp;
    cudaGetSymbolAddress(&pv, g_coff); coffp = (int*)pv;

    const int gN  = (NN + NT - 1) / NT;
    const int gE  = (EE + NT - 1) / NT;
    const int gNw = (NN*32 + NT - 1) / NT;
    const int gG  = (NN + 127) / 128;

    k_init<<<gN, NT>>>();
    k_cnt0<<<gE, NT>>>(e0);

    const float* Xin[3]  = { x_in, p_xa, p_xb };
    float*       memb[3] = { p_m0, p_m1, p_m2 };
    float*       xout[3] = { p_xa, p_xb, p_xa };

    for (int i = 0; i < 3; i++) {
        int t = i;
        k_scanA<<<NB, 256>>>(p_cnt, coffp + t*NN);
        if (i == 0) k_gemmT<<<gG, 256>>>(x_in, Wd[0], p_xw, -1, 0);
        else        k_gemmT<<<gG, 256>>>(Xin[i], Wd[i], p_xw, i-1, 1);
        k_scan3f<<<NB, 256>>>(t);
        k_fill<<<gE, NT>>>(t, e0);
        if (i == 0) k_conv<<<gNw, NT>>>(0, bd[0], memb[0], 1, Wp[0]);   // capture index 6 -> profiled
        else        k_conv_act<<<NBW, NT>>>(t, i-1, bd[i], memb[i], 1, Wp[i], 0, (const int*)0);
        k_score_union<<<gE, NT>>>(t, bp[i], e0);
        k_flatten<<<gN, NT>>>(i);
        cudaMemsetAsync(p_htab, 0xFF, HSZ*sizeof(unsigned));
        k_seg_relabel<<<gE, NT>>>(t, i, bp[i], e0);
        k_scanA<<<NB, 256>>>(p_mcnt, p_moff);
        k_mscan3<<<NB, 256>>>();
        k_mfill<<<gN, NT>>>(i, xout[i]);
        k_poolacc<<<gG, 256>>>(i, memb[i], xout[i]);
    }

    // ---- bottom conv (topology 3, rows act[2]) ----
    k_scanA<<<NB, 256>>>(p_cnt, coffp + 3*NN);
    k_gemmT<<<gG, 256>>>(p_xa, Wd[3], p_xw, 2, 1);
    k_scan3f<<<NB, 256>>>(3);
    k_fill<<<gE, NT>>>(3, e0);
    k_conv_act<<<NBW, NT>>>(3, 2, bd[3], p_cv, 0, (const float*)0, 0, (const int*)0);

    // ---- UP 0 : rows act[1], topology 2 ----
    k_gemmT<<<gG, 256>>>(p_m2, Wu[0], p_xw, 1, 0);
    k_gemmT<<<gG, 256>>>(p_cv, Wu[0] + 128*HD, p_yb, 2, 0);
    k_conv_act<<<NBW, NT>>>(2, 1, bu[0], p_xa, 1, (const float*)0, 1, p_cl + 2*NN);

    // ---- UP 1 : rows act[0], topology 1 ----
    k_gemmT<<<gG, 256>>>(p_m1, Wu[1], p_xw, 0, 0);
    k_gemmT<<<gG, 256>>>(p_xa, Wu[1] + 128*HD, p_yb, 1, 0);
    k_conv_act<<<NBW, NT>>>(1, 0, bu[1], p_xb, 1, (const float*)0, 1, p_cl + 1*NN);

    // ---- UP 2 : full N, topology 0, output dim 1 ----
    k_yb2<<<NBW, NT>>>(p_xb, Wu[2] + 256);
    k_xw1<<<gNw, NT>>>(p_m0, x_in, Wu[2]);
    k_conv1<<<gNw, NT>>>(bu[2], out);
}